// round 2
// baseline (speedup 1.0000x reference)
#include <cuda_runtime.h>
#include <cstdint>
#include <math.h>

// Problem constants
#define BB    2
#define NN    2048
#define KK    32
#define HH    128
#define NODES 4096          // B*N
#define EDGES 131072        // B*N*K
#define PAD   130           // smem row stride (floats) for 128-wide tiles

// ---------------- scratch (static device globals; no runtime alloc) ----------
__device__ float g_he [EDGES * HH];   // 64 MiB: normalized edge embeddings
__device__ float g_h  [NODES * HH];   // current node state
__device__ float g_P1 [NODES * HH];   // h@W1 + b1
__device__ float g_P23[NODES * HH];   // h@W2 + hS@W3

// ---------------- packed f32x2 helpers --------------------------------------
__device__ __forceinline__ void ffma2(unsigned long long &c,
                                      unsigned long long a,
                                      unsigned long long b) {
    asm("fma.rn.f32x2 %0, %1, %2, %0;" : "+l"(c) : "l"(a), "l"(b));
}
__device__ __forceinline__ unsigned long long pack2(float a) {
    unsigned long long r;
    asm("mov.b64 %0, {%1, %1};" : "=l"(r) : "f"(a));
    return r;
}
__device__ __forceinline__ float2 u2f(unsigned long long u) {
    float2 f;
    asm("mov.b64 {%0, %1}, %2;" : "=f"(f.x), "=f"(f.y) : "l"(u));
    return f;
}

// 128x128 (K=128) block GEMM: out[r][j] += sum_kk sA[r*PAD+kk] * sW[kk*128+j]
// thread mapping: 256 threads, j0=(tid&15)*8 cols, r0=(tid>>4)*8 rows
__device__ __forceinline__ void gemm_tile(const float* __restrict__ sA,
                                          const float* __restrict__ sW,
                                          int r0, int j0,
                                          unsigned long long acc[8][4]) {
#pragma unroll 4
    for (int kk = 0; kk < 128; ++kk) {
        ulonglong2 w01 = *reinterpret_cast<const ulonglong2*>(sW + kk * 128 + j0);
        ulonglong2 w23 = *reinterpret_cast<const ulonglong2*>(sW + kk * 128 + j0 + 4);
#pragma unroll
        for (int i = 0; i < 8; ++i) {
            unsigned long long a2 = pack2(sA[(r0 + i) * PAD + kk]);
            ffma2(acc[i][0], a2, w01.x);
            ffma2(acc[i][1], a2, w01.y);
            ffma2(acc[i][2], a2, w23.x);
            ffma2(acc[i][3], a2, w23.y);
        }
    }
}

__device__ __forceinline__ void zero_acc(unsigned long long acc[8][4]) {
#pragma unroll
    for (int i = 0; i < 8; ++i)
#pragma unroll
        for (int c = 0; c < 4; ++c) acc[i][c] = 0ull;
}

// load 128x128 f32 tile (contiguous) into padded smem
__device__ __forceinline__ void load_tile_pad(float* dst, const float* __restrict__ src, int tid) {
    for (int i = tid * 2; i < 128 * 128; i += 512) {
        float2 v = *reinterpret_cast<const float2*>(src + i);
        int r = i >> 7, c = i & 127;
        *reinterpret_cast<float2*>(dst + r * PAD + c) = v;
    }
}
// load 128x128 f32 weights (contiguous, unpadded)
__device__ __forceinline__ void load_w(float* dst, const float* __restrict__ src, int tid) {
    for (int i = tid * 4; i < 128 * 128; i += 1024)
        *reinterpret_cast<float4*>(dst + i) = *reinterpret_cast<const float4*>(src + i);
}

// ---------------- kernel 1: node embedding + norm ----------------------------
// h0 = norm(V @ Wv + b), one block (128 thr) per node row
__global__ void embed_node_kernel(const float* __restrict__ V,
                                  const float* __restrict__ W,
                                  const float* __restrict__ b,
                                  const float* __restrict__ g,
                                  const float* __restrict__ b2) {
    int row = blockIdx.x;
    int j = threadIdx.x;
    const float* v = V + row * 64;
    float acc = b[j];
#pragma unroll
    for (int k = 0; k < 64; ++k) acc = fmaf(__ldg(v + k), __ldg(W + k * HH + j), acc);

    __shared__ float red[8];
    float s = acc;
#pragma unroll
    for (int o = 16; o; o >>= 1) s += __shfl_xor_sync(0xffffffffu, s, o);
    int w = j >> 5, l = j & 31;
    if (l == 0) red[w] = s;
    __syncthreads();
    float mu = (red[0] + red[1] + red[2] + red[3]) * (1.f / 128.f);
    float d = acc - mu;
    float ss = d * d;
#pragma unroll
    for (int o = 16; o; o >>= 1) ss += __shfl_xor_sync(0xffffffffu, ss, o);
    if (l == 0) red[4 + w] = ss;
    __syncthreads();
    float var = (red[4] + red[5] + red[6] + red[7]) * (1.f / 127.f);
    float sigma = sqrtf(var);
    g_h[row * HH + j] = g[j] * d / (sigma + 1e-6f) + b2[j];
}

// ---------------- kernel 2: edge embedding + norm ----------------------------
// he = norm(E @ We + b), one block (128 thr) per edge row
__global__ void embed_edge_kernel(const float* __restrict__ E,
                                  const float* __restrict__ W,
                                  const float* __restrict__ b,
                                  const float* __restrict__ g,
                                  const float* __restrict__ b2) {
    int row = blockIdx.x;
    int j = threadIdx.x;
    const float* e = E + row * 48;
    float acc = b[j];
#pragma unroll
    for (int k = 0; k < 48; ++k) acc = fmaf(__ldg(e + k), __ldg(W + k * HH + j), acc);

    __shared__ float red[8];
    float s = acc;
#pragma unroll
    for (int o = 16; o; o >>= 1) s += __shfl_xor_sync(0xffffffffu, s, o);
    int w = j >> 5, l = j & 31;
    if (l == 0) red[w] = s;
    __syncthreads();
    float mu = (red[0] + red[1] + red[2] + red[3]) * (1.f / 128.f);
    float d = acc - mu;
    float ss = d * d;
#pragma unroll
    for (int o = 16; o; o >>= 1) ss += __shfl_xor_sync(0xffffffffu, ss, o);
    if (l == 0) red[4 + w] = ss;
    __syncthreads();
    float var = (red[4] + red[5] + red[6] + red[7]) * (1.f / 127.f);
    float sigma = sqrtf(var);
    g_he[row * HH + j] = g[j] * d / (sigma + 1e-6f) + b2[j];
}

// ---------------- kernel 3: per-layer node projections -----------------------
// y==0: P1  = h @ W1 + b1
// y==1: P23 = h @ W2 + hS @ W3
__global__ void __launch_bounds__(256, 1)
node_proj_kernel(const float* __restrict__ hS,
                 const float* __restrict__ Lw1,
                 const float* __restrict__ Lb1,
                 int layer) {
    extern __shared__ float sm[];
    float* sW = sm;
    float* sA = sm + 128 * 128;

    int tid = threadIdx.x;
    int base = blockIdx.x * 128;            // row base (node index)
    int which = blockIdx.y;
    const float* Wbase = Lw1 + (size_t)layer * 512 * 128;

    load_tile_pad(sA, g_h + (size_t)base * 128, tid);
    load_w(sW, Wbase + (which == 0 ? 0 : 128 * 128), tid);
    __syncthreads();

    int j0 = (tid & 15) * 8;
    int r0 = (tid >> 4) * 8;
    unsigned long long acc[8][4];
    zero_acc(acc);
    gemm_tile(sA, sW, r0, j0, acc);

    if (which == 1) {
        __syncthreads();
        load_tile_pad(sA, hS + (size_t)base * 128, tid);
        load_w(sW, Wbase + 256 * 128, tid);
        __syncthreads();
        gemm_tile(sA, sW, r0, j0, acc);     // accumulate
    }

    float bias[8];
    if (which == 0) {
        const float* b1 = Lb1 + layer * 128;
#pragma unroll
        for (int c = 0; c < 8; ++c) bias[c] = b1[j0 + c];
    } else {
#pragma unroll
        for (int c = 0; c < 8; ++c) bias[c] = 0.f;
    }
    float* out = (which == 0) ? g_P1 : g_P23;
#pragma unroll
    for (int i = 0; i < 8; ++i) {
        float2 a0 = u2f(acc[i][0]), a1 = u2f(acc[i][1]);
        float2 a2 = u2f(acc[i][2]), a3 = u2f(acc[i][3]);
        float4 o0 = make_float4(a0.x + bias[0], a0.y + bias[1], a1.x + bias[2], a1.y + bias[3]);
        float4 o1 = make_float4(a2.x + bias[4], a2.y + bias[5], a3.x + bias[6], a3.y + bias[7]);
        float* dst = out + (size_t)(base + r0 + i) * 128 + j0;
        *reinterpret_cast<float4*>(dst) = o0;
        *reinterpret_cast<float4*>(dst + 4) = o1;
    }
}

// ---------------- kernel 4: fused edge MLP + aggregate + residual norm -------
// One block = 4 nodes = 128 edge rows. Three chained 128x128x128 GEMMs in smem.
__global__ void __launch_bounds__(256, 1)
edge_layer_kernel(const int* __restrict__ Eidx,
                  const float* __restrict__ mask,
                  const float* __restrict__ Lw1,
                  const float* __restrict__ Lw2,
                  const float* __restrict__ Lw3,
                  const float* __restrict__ Lb2,
                  const float* __restrict__ Lb3,
                  const float* __restrict__ Lng,
                  const float* __restrict__ Lnb,
                  int layer,
                  float* h_out_opt) {
    extern __shared__ float sm[];
    float* sW    = sm;                     // 16384
    float* sA    = sW + 16384;             // 128*PAD = 16640
    float* sP1   = sA + 128 * PAD;         // 512
    float* sHold = sP1 + 512;              // 512
    float* sDh   = sHold + 512;            // 512
    float* sB2   = sDh + 512;              // 128
    float* sB3   = sB2 + 128;              // 128
    float* sVm   = sB3 + 128;              // 128
    int*   sGidx = reinterpret_cast<int*>(sVm + 128); // 128

    int tid = threadIdx.x;
    int base = blockIdx.x * 4;             // node base

    // ---- prologue
    if (tid < 128) {
        int r = tid;
        int nd = base + (r >> 5);
        int b = nd >> 11;
        int idx = Eidx[nd * 32 + (r & 31)];
        int gi = (b << 11) + idx;
        sGidx[r] = gi;
        sVm[r] = mask[gi];
        sB2[r] = Lb2[layer * 128 + r];
        sB3[r] = Lb3[layer * 128 + r];
    }
    for (int i = tid; i < 512; i += 256) {
        sP1[i]   = g_P1[(size_t)base * 128 + i];
        sHold[i] = g_h [(size_t)base * 128 + i];
    }
    load_tile_pad(sA, g_he + (size_t)base * 32 * 128, tid);      // he tile (128 rows)
    load_w(sW, Lw1 + (size_t)layer * 512 * 128 + 384 * 128, tid); // W4
    __syncthreads();

    int j0 = (tid & 15) * 8;
    int r0 = (tid >> 4) * 8;
    unsigned long long acc[8][4];

    // ---- GEMM1: pre = he@W4 (+ P1[node] + P23[gather] + relu in epilogue)
    zero_acc(acc);
    gemm_tile(sA, sW, r0, j0, acc);
    __syncthreads();
#pragma unroll
    for (int i = 0; i < 8; ++i) {
        int r = r0 + i;
        const float* p23 = g_P23 + (size_t)sGidx[r] * 128 + j0;
        float4 q0 = *reinterpret_cast<const float4*>(p23);
        float4 q1 = *reinterpret_cast<const float4*>(p23 + 4);
        const float* p1 = sP1 + ((r >> 5) << 7) + j0;
        float2 a0 = u2f(acc[i][0]), a1 = u2f(acc[i][1]);
        float2 a2 = u2f(acc[i][2]), a3 = u2f(acc[i][3]);
        float2 o0 = make_float2(fmaxf(a0.x + q0.x + p1[0], 0.f), fmaxf(a0.y + q0.y + p1[1], 0.f));
        float2 o1 = make_float2(fmaxf(a1.x + q0.z + p1[2], 0.f), fmaxf(a1.y + q0.w + p1[3], 0.f));
        float2 o2 = make_float2(fmaxf(a2.x + q1.x + p1[4], 0.f), fmaxf(a2.y + q1.y + p1[5], 0.f));
        float2 o3 = make_float2(fmaxf(a3.x + q1.z + p1[6], 0.f), fmaxf(a3.y + q1.w + p1[7], 0.f));
        float* dst = sA + r * PAD + j0;
        *reinterpret_cast<float2*>(dst)     = o0;
        *reinterpret_cast<float2*>(dst + 2) = o1;
        *reinterpret_cast<float2*>(dst + 4) = o2;
        *reinterpret_cast<float2*>(dst + 6) = o3;
    }
    load_w(sW, Lw2 + (size_t)layer * 128 * 128, tid);
    __syncthreads();

    // ---- GEMM2: m2 = relu(m1@Lw2 + b2)
    zero_acc(acc);
    gemm_tile(sA, sW, r0, j0, acc);
    __syncthreads();
#pragma unroll
    for (int i = 0; i < 8; ++i) {
        int r = r0 + i;
        float2 a0 = u2f(acc[i][0]), a1 = u2f(acc[i][1]);
        float2 a2 = u2f(acc[i][2]), a3 = u2f(acc[i][3]);
        const float* b2p = sB2 + j0;
        float2 o0 = make_float2(fmaxf(a0.x + b2p[0], 0.f), fmaxf(a0.y + b2p[1], 0.f));
        float2 o1 = make_float2(fmaxf(a1.x + b2p[2], 0.f), fmaxf(a1.y + b2p[3], 0.f));
        float2 o2 = make_float2(fmaxf(a2.x + b2p[4], 0.f), fmaxf(a2.y + b2p[5], 0.f));
        float2 o3 = make_float2(fmaxf(a3.x + b2p[6], 0.f), fmaxf(a3.y + b2p[7], 0.f));
        float* dst = sA + r * PAD + j0;
        *reinterpret_cast<float2*>(dst)     = o0;
        *reinterpret_cast<float2*>(dst + 2) = o1;
        *reinterpret_cast<float2*>(dst + 4) = o2;
        *reinterpret_cast<float2*>(dst + 6) = o3;
    }
    load_w(sW, Lw3 + (size_t)layer * 128 * 128, tid);
    __syncthreads();

    // ---- GEMM3: m3 = (m2@Lw3 + b3) * vmask
    zero_acc(acc);
    gemm_tile(sA, sW, r0, j0, acc);
    __syncthreads();
#pragma unroll
    for (int i = 0; i < 8; ++i) {
        int r = r0 + i;
        float vm = sVm[r];
        float2 a0 = u2f(acc[i][0]), a1 = u2f(acc[i][1]);
        float2 a2 = u2f(acc[i][2]), a3 = u2f(acc[i][3]);
        const float* b3p = sB3 + j0;
        float2 o0 = make_float2((a0.x + b3p[0]) * vm, (a0.y + b3p[1]) * vm);
        float2 o1 = make_float2((a1.x + b3p[2]) * vm, (a1.y + b3p[3]) * vm);
        float2 o2 = make_float2((a2.x + b3p[4]) * vm, (a2.y + b3p[5]) * vm);
        float2 o3 = make_float2((a3.x + b3p[6]) * vm, (a3.y + b3p[7]) * vm);
        float* dst = sA + r * PAD + j0;
        *reinterpret_cast<float2*>(dst)     = o0;
        *reinterpret_cast<float2*>(dst + 2) = o1;
        *reinterpret_cast<float2*>(dst + 4) = o2;
        *reinterpret_cast<float2*>(dst + 6) = o3;
    }
    __syncthreads();

    // ---- segment sum over K=32 edges per node -> dh
    for (int p = tid; p < 512; p += 256) {
        int g = p >> 7, j = p & 127;
        const float* col = sA + (g * 32) * PAD + j;
        float s = 0.f;
#pragma unroll
        for (int r = 0; r < 32; ++r) s += col[r * PAD];
        sDh[p] = s * (1.f / 30.f);
    }
    __syncthreads();

    // ---- residual + layernorm (ddof=1) + mask; warp per node
    float* hout = h_out_opt ? h_out_opt : g_h;
    int w = tid >> 5, l = tid & 31;
    if (w < 4) {
        int nd = base + w;
        float x[4], sum = 0.f;
#pragma unroll
        for (int c = 0; c < 4; ++c) {
            int j = l + 32 * c;
            x[c] = sHold[w * 128 + j] + sDh[w * 128 + j];
            sum += x[c];
        }
#pragma unroll
        for (int o = 16; o; o >>= 1) sum += __shfl_xor_sync(0xffffffffu, sum, o);
        float mu = sum * (1.f / 128.f);
        float ss = 0.f;
#pragma unroll
        for (int c = 0; c < 4; ++c) {
            float d = x[c] - mu;
            ss += d * d;
        }
#pragma unroll
        for (int o = 16; o; o >>= 1) ss += __shfl_xor_sync(0xffffffffu, ss, o);
        float sigma = sqrtf(ss * (1.f / 127.f));
        float inv = 1.f / (sigma + 1e-6f);
        float mk = mask[nd];
#pragma unroll
        for (int c = 0; c < 4; ++c) {
            int j = l + 32 * c;
            float v = (Lng[layer * 128 + j] * (x[c] - mu) * inv + Lnb[layer * 128 + j]) * mk;
            hout[(size_t)nd * 128 + j] = v;
        }
    }
}

// ---------------- launch ------------------------------------------------------
extern "C" void kernel_launch(void* const* d_in, const int* in_sizes, int n_in,
                              void* d_out, int out_size) {
    const float* V     = (const float*)d_in[0];
    const float* E     = (const float*)d_in[1];
    const float* hS    = (const float*)d_in[2];
    const int*   E_idx = (const int*)  d_in[3];
    const float* mask  = (const float*)d_in[4];
    const float* Wv_w  = (const float*)d_in[5];
    const float* Wv_b  = (const float*)d_in[6];
    const float* Wv_g  = (const float*)d_in[7];
    const float* Wv_b2 = (const float*)d_in[8];
    const float* We_w  = (const float*)d_in[9];
    const float* We_b  = (const float*)d_in[10];
    const float* We_g  = (const float*)d_in[11];
    const float* We_b2 = (const float*)d_in[12];
    const float* Lw1   = (const float*)d_in[13];
    const float* Lb1   = (const float*)d_in[14];
    const float* Lw2   = (const float*)d_in[15];
    const float* Lb2   = (const float*)d_in[16];
    const float* Lw3   = (const float*)d_in[17];
    const float* Lb3   = (const float*)d_in[18];
    const float* Ln_g  = (const float*)d_in[19];
    const float* Ln_b  = (const float*)d_in[20];
    float* out = (float*)d_out;

    const int PROJ_SMEM = (128 * 128 + 128 * PAD) * 4;                       // 132096
    const int EDGE_SMEM = (128 * 128 + 128 * PAD + 512 * 3 + 128 * 3 + 128) * 4; // 140288
    cudaFuncSetAttribute(node_proj_kernel,  cudaFuncAttributeMaxDynamicSharedMemorySize, PROJ_SMEM);
    cudaFuncSetAttribute(edge_layer_kernel, cudaFuncAttributeMaxDynamicSharedMemorySize, EDGE_SMEM);

    embed_node_kernel<<<NODES, 128>>>(V, Wv_w, Wv_b, Wv_g, Wv_b2);
    embed_edge_kernel<<<EDGES, 128>>>(E, We_w, We_b, We_g, We_b2);

    for (int layer = 0; layer < 3; ++layer) {
        node_proj_kernel<<<dim3(NODES / 128, 2), 256, PROJ_SMEM>>>(hS, Lw1, Lb1, layer);
        float* hdst = (layer == 2) ? out : nullptr;   // nullptr -> write g_h in-place
        edge_layer_kernel<<<NODES / 4, 256, EDGE_SMEM>>>(
            E_idx, mask, Lw1, Lw2, Lw3, Lb2, Lb3, Ln_g, Ln_b, layer, hdst);
    }
}

// round 4
// speedup vs baseline: 3.3566x; 3.3566x over previous
#include <cuda_runtime.h>
#include <cstdint>
#include <math.h>

#define NODES 4096
#define EDGES 131072

// ---------------- device scratch (static globals) ----------------
__device__ float g_her[EDGES * 128];  // tf32-rounded edge embeddings, row-major
__device__ float g_h  [NODES * 128];  // exact node state
__device__ float g_hr [NODES * 128];  // tf32-rounded node state
__device__ float g_hSr[NODES * 128];  // tf32-rounded hS
__device__ float g_P1 [NODES * 128];
__device__ float g_P23[NODES * 128];
__device__ float g_Wt [20 * 16384];   // weights as Bt[n][k], tf32-rounded

// ---------------- helpers ----------------
__device__ __forceinline__ uint32_t s2u(const void* p) {
    uint32_t a;
    asm("{ .reg .u64 t; cvta.to.shared.u64 t, %1; cvt.u32.u64 %0, t; }" : "=r"(a) : "l"(p));
    return a;
}
__device__ __forceinline__ float ttf(float x) {   // round f32 -> tf32 (rna)
    uint32_t u;
    asm("cvt.rna.tf32.f32 %0, %1;" : "=r"(u) : "f"(x));
    return __uint_as_float(u);
}
__device__ __forceinline__ void ldsm4(uint32_t d[4], uint32_t a) {
    asm volatile("ldmatrix.sync.aligned.m8n8.x4.shared.b16 {%0,%1,%2,%3}, [%4];"
                 : "=r"(d[0]), "=r"(d[1]), "=r"(d[2]), "=r"(d[3]) : "r"(a));
}
__device__ __forceinline__ void mma8(float d[4], const uint32_t a[4], uint32_t b0, uint32_t b1) {
    asm volatile("mma.sync.aligned.m16n8k8.row.col.f32.tf32.tf32.f32 "
                 "{%0,%1,%2,%3}, {%4,%5,%6,%7}, {%8,%9}, {%0,%1,%2,%3};"
                 : "+f"(d[0]), "+f"(d[1]), "+f"(d[2]), "+f"(d[3])
                 : "r"(a[0]), "r"(a[1]), "r"(a[2]), "r"(a[3]), "r"(b0), "r"(b1));
}
#define CP16(dst, src) asm volatile("cp.async.cg.shared.global [%0], [%1], 16;" :: "r"(dst), "l"(src))
#define CP_COMMIT()    asm volatile("cp.async.commit_group;")
#define CP_WAIT0()     asm volatile("cp.async.wait_group 0;" ::: "memory")

// swizzled float index within a 128 x ROWF tile (XOR on 16B granules)
template <int ROWF>
__device__ __forceinline__ int swz(int r, int c) { return r * ROWF + (c ^ ((r & 7) << 2)); }

// cp.async copy of a 128 x (KSTEPS*8) f32 tile, row-major contiguous src
template <int KSTEPS>
__device__ __forceinline__ void cpa_tile(uint32_t sDst, const float* __restrict__ g, int tid) {
    const int ROWF = KSTEPS * 8;
    const int NF4 = 128 * ROWF / 4;
    #pragma unroll 4
    for (int i = tid; i < NF4; i += 256) {
        int r = i / (ROWF / 4), c = (i % (ROWF / 4)) * 4;
        CP16(sDst + (swz<ROWF>(r, c) << 2), g + i * 4);
    }
}

// CTA GEMM: D[128,128] (+)= A[128,K] @ Bt[128,K]^T ; 8 warps, warp tile 32x64
template <int KSTEPS>
__device__ __forceinline__ void cta_gemm(uint32_t sAu, uint32_t sBu, int lane,
                                         int mbase, int nbase, float acc[2][8][4]) {
    const int ROWF = KSTEPS * 8;
    int ar = lane & 15;
    int ac = (lane >> 4) << 2;
    int br = (lane & 7) + ((lane >> 4) << 3);
    int bc = (lane & 8) ? 4 : 0;
    #pragma unroll
    for (int k0 = 0; k0 < KSTEPS; ++k0) {
        uint32_t a[2][4];
        #pragma unroll
        for (int mt = 0; mt < 2; ++mt) {
            int r = mbase + mt * 16 + ar, c = k0 * 8 + ac;
            ldsm4(a[mt], sAu + (swz<ROWF>(r, c) << 2));
        }
        #pragma unroll
        for (int q = 0; q < 4; ++q) {
            int r = nbase + q * 16 + br, c = k0 * 8 + bc;
            uint32_t b[4];
            ldsm4(b, sBu + (swz<ROWF>(r, c) << 2));
            mma8(acc[0][q * 2],     a[0], b[0], b[1]);
            mma8(acc[0][q * 2 + 1], a[0], b[2], b[3]);
            mma8(acc[1][q * 2],     a[1], b[0], b[1]);
            mma8(acc[1][q * 2 + 1], a[1], b[2], b[3]);
        }
    }
}
__device__ __forceinline__ void zacc(float acc[2][8][4]) {
    #pragma unroll
    for (int i = 0; i < 2; ++i)
        #pragma unroll
        for (int j = 0; j < 8; ++j)
            #pragma unroll
            for (int k = 0; k < 4; ++k) acc[i][j][k] = 0.f;
}

// ---------------- pack: weights -> Bt[n][k] tf32 ----------------
__global__ void pack_w(const float* __restrict__ Wv, const float* __restrict__ We,
                       const float* __restrict__ Lw1, const float* __restrict__ Lw2,
                       const float* __restrict__ Lw3) {
    int m = blockIdx.x;
    const float* src; int Kin, ROWF;
    if (m == 0)      { src = Wv; Kin = 64; ROWF = 64; }
    else if (m == 1) { src = We; Kin = 48; ROWF = 64; }
    else {
        int l = (m - 2) / 6, q = (m - 2) % 6;
        if (q < 4)       src = Lw1 + ((size_t)l * 512 + q * 128) * 128;
        else if (q == 4) src = Lw2 + (size_t)l * 16384;
        else             src = Lw3 + (size_t)l * 16384;
        Kin = 128; ROWF = 128;
    }
    float* dst = g_Wt + (size_t)m * 16384;
    int tot = 128 * ROWF;
    for (int i = threadIdx.x; i < tot; i += blockDim.x) {
        int n = i / ROWF, k = i % ROWF;
        dst[i] = (k < Kin) ? ttf(src[(size_t)k * 128 + n]) : 0.f;
    }
}
__global__ void pack_hs(const float* __restrict__ hS) {
    for (int i = blockIdx.x * blockDim.x + threadIdx.x; i < NODES * 128;
         i += gridDim.x * blockDim.x)
        g_hSr[i] = ttf(hS[i]);
}

// ---------------- embed: norm(X@W + b) via mma.sync, K=64 ----------------
// smem floats: sA 0(8192) sW 8192(8192) sS 16384(128*129) sBias 32896 sG 33024
// sB2 33152 sMu 33280 sInv 33408  -> 33536 floats
#define SM_EMB (33536 * 4)
template <int KIN, int MODE>  // MODE 0: node (g_h + g_hr), 1: edge (g_her)
__global__ void __launch_bounds__(256, 1)
embed_k(const float* __restrict__ X, const float* __restrict__ bb,
        const float* __restrict__ gg, const float* __restrict__ b2, int wslot) {
    extern __shared__ float sm[];
    float* sA = sm; float* sW = sm + 8192; float* sS = sm + 16384;
    float* sBias = sm + 32896; float* sG = sm + 33024; float* sB2 = sm + 33152;
    float* sMu = sm + 33280; float* sInv = sm + 33408;
    uint32_t sAu = s2u(sA), sWu = s2u(sW);
    int tid = threadIdx.x, lane = tid & 31, wid = tid >> 5, blk = blockIdx.x;

    cpa_tile<8>(sWu, g_Wt + (size_t)wslot * 16384, tid);
    CP_COMMIT();
    // A: load + round + swizzle-store (zero pad K to 64)
    for (int i = tid; i < 2048; i += 256) {
        int r = i >> 4, c4 = i & 15;
        float4 v;
        if (c4 * 4 < KIN) {
            v = *(const float4*)(X + ((size_t)blk * 128 + r) * KIN + c4 * 4);
            v.x = ttf(v.x); v.y = ttf(v.y); v.z = ttf(v.z); v.w = ttf(v.w);
        } else v = make_float4(0.f, 0.f, 0.f, 0.f);
        *(float4*)(sA + swz<64>(r, c4 * 4)) = v;
    }
    if (tid < 128) { sBias[tid] = bb[tid]; sG[tid] = gg[tid]; sB2[tid] = b2[tid]; }
    CP_WAIT0(); __syncthreads();

    float acc[2][8][4];
    zacc(acc);
    int mbase = (wid & 3) * 32, nbase = (wid >> 2) * 64;
    cta_gemm<8>(sAu, sWu, lane, mbase, nbase, acc);

    // epilogue: D + bias -> sS (stride 129)
    int g = lane >> 2, t = lane & 3;
    #pragma unroll
    for (int mt = 0; mt < 2; ++mt) {
        int r0 = mbase + mt * 16 + g;
        #pragma unroll
        for (int nt = 0; nt < 8; ++nt) {
            int c0 = nbase + nt * 8 + t * 2;
            float* d = acc[mt][nt];
            sS[r0 * 129 + c0]           = d[0] + sBias[c0];
            sS[r0 * 129 + c0 + 1]       = d[1] + sBias[c0 + 1];
            sS[(r0 + 8) * 129 + c0]     = d[2] + sBias[c0];
            sS[(r0 + 8) * 129 + c0 + 1] = d[3] + sBias[c0 + 1];
        }
    }
    __syncthreads();
    if (tid < 128) {
        const float* row = sS + tid * 129;
        float sum = 0.f;
        #pragma unroll 8
        for (int j = 0; j < 128; ++j) sum += row[j];
        float mu = sum * (1.f / 128.f);
        float ss = 0.f;
        #pragma unroll 8
        for (int j = 0; j < 128; ++j) { float dd = row[j] - mu; ss += dd * dd; }
        sMu[tid] = mu;
        sInv[tid] = 1.f / (sqrtf(ss * (1.f / 127.f)) + 1e-6f);
    }
    __syncthreads();
    for (int i = tid; i < 4096; i += 256) {
        int r = i >> 5, j = (i & 31) * 4;
        float mu = sMu[r], inv = sInv[r];
        float4 o, q;
        const float* row = sS + r * 129 + j;
        o.x = sG[j]     * (row[0] - mu) * inv + sB2[j];
        o.y = sG[j + 1] * (row[1] - mu) * inv + sB2[j + 1];
        o.z = sG[j + 2] * (row[2] - mu) * inv + sB2[j + 2];
        o.w = sG[j + 3] * (row[3] - mu) * inv + sB2[j + 3];
        q.x = ttf(o.x); q.y = ttf(o.y); q.z = ttf(o.z); q.w = ttf(o.w);
        size_t off = ((size_t)blk * 128 + r) * 128 + j;
        if (MODE == 0) {
            *(float4*)(g_h + off) = o;
            *(float4*)(g_hr + off) = q;
        } else {
            *(float4*)(g_her + off) = q;
        }
    }
}

// ---------------- node projections ----------------
// y==0: P1 = h@W1q0 + b1 ; y==1: P23 = h@W1q1 + hS@W1q2
// smem: sA 0(16384) sW0 16384 sW1 32768 sBias 49152 -> 49280 floats
#define SM_PROJ (49280 * 4)
__global__ void __launch_bounds__(256, 1)
node_proj_k(const float* __restrict__ Lb1, int layer) {
    extern __shared__ float sm[];
    float* sA = sm; float* sW0 = sm + 16384; float* sW1 = sm + 32768;
    float* sBias = sm + 49152;
    uint32_t sAu = s2u(sA), sW0u = s2u(sW0), sW1u = s2u(sW1);
    int tid = threadIdx.x, lane = tid & 31, wid = tid >> 5;
    int blk = blockIdx.x, which = blockIdx.y;
    int wbase = 2 + layer * 6;

    cpa_tile<16>(sAu, g_hr + (size_t)blk * 16384, tid);
    cpa_tile<16>(sW0u, g_Wt + (size_t)(wbase + (which ? 1 : 0)) * 16384, tid);
    if (which) cpa_tile<16>(sW1u, g_Wt + (size_t)(wbase + 2) * 16384, tid);
    CP_COMMIT();
    if (tid < 128) sBias[tid] = which ? 0.f : Lb1[layer * 128 + tid];
    CP_WAIT0(); __syncthreads();

    float acc[2][8][4];
    zacc(acc);
    int mbase = (wid & 3) * 32, nbase = (wid >> 2) * 64;
    cta_gemm<16>(sAu, sW0u, lane, mbase, nbase, acc);

    if (which) {
        __syncthreads();                       // everyone done reading sA
        cpa_tile<16>(sAu, g_hSr + (size_t)blk * 16384, tid);
        CP_COMMIT(); CP_WAIT0(); __syncthreads();
        cta_gemm<16>(sAu, sW1u, lane, mbase, nbase, acc);
    }

    float* out = which ? g_P23 : g_P1;
    int g = lane >> 2, t = lane & 3;
    #pragma unroll
    for (int mt = 0; mt < 2; ++mt) {
        int r0 = mbase + mt * 16 + g;
        #pragma unroll
        for (int nt = 0; nt < 8; ++nt) {
            int c0 = nbase + nt * 8 + t * 2;
            float* d = acc[mt][nt];
            float2 o0 = make_float2(d[0] + sBias[c0], d[1] + sBias[c0 + 1]);
            float2 o1 = make_float2(d[2] + sBias[c0], d[3] + sBias[c0 + 1]);
            *(float2*)(out + ((size_t)blk * 128 + r0) * 128 + c0) = o0;
            *(float2*)(out + ((size_t)blk * 128 + r0 + 8) * 128 + c0) = o1;
        }
    }
}

// ---------------- fused edge layer ----------------
// smem floats: sA 0(16384) sB0 16384 sB1 32768 sP1 49152(512) sHold 49664(512)
// sDh 50176(512) sVm 50688(128) sBb2 50816(128) sBb3 50944(128) sGidx 51072(128)
#define SM_EDGE (51200 * 4)
__global__ void __launch_bounds__(256, 1)
edge_layer_k(const int* __restrict__ Eidx, const float* __restrict__ mask,
             const float* __restrict__ Lb2, const float* __restrict__ Lb3,
             const float* __restrict__ Lng, const float* __restrict__ Lnb,
             int layer, int last, float* __restrict__ outp) {
    extern __shared__ float sm[];
    float* sA = sm; float* sB0 = sm + 16384; float* sB1 = sm + 32768;
    float* sP1 = sm + 49152; float* sHold = sm + 49664; float* sDh = sm + 50176;
    float* sVm = sm + 50688; float* sBb2 = sm + 50816; float* sBb3 = sm + 50944;
    int* sGidx = (int*)(sm + 51072);
    uint32_t sAu = s2u(sA), sB0u = s2u(sB0), sB1u = s2u(sB1);

    int tid = threadIdx.x, lane = tid & 31, wid = tid >> 5, blk = blockIdx.x;
    int base4 = blk * 4;
    int wbase = 2 + layer * 6;

    cpa_tile<16>(sAu, g_her + (size_t)blk * 16384, tid);
    cpa_tile<16>(sB0u, g_Wt + (size_t)(wbase + 3) * 16384, tid);   // W1q3 (he)
    cpa_tile<16>(sB1u, g_Wt + (size_t)(wbase + 4) * 16384, tid);   // Lw2
    CP_COMMIT();

    if (tid < 128) {
        int nd = base4 + (tid >> 5);
        int idx = Eidx[nd * 32 + (tid & 31)];
        int gi = ((nd >> 11) << 11) + idx;
        sGidx[tid] = gi;
        sVm[tid] = mask[gi];
        sBb2[tid] = Lb2[layer * 128 + tid];
        sBb3[tid] = Lb3[layer * 128 + tid];
    }
    for (int i = tid; i < 512; i += 256) {
        sP1[i]   = g_P1[(size_t)base4 * 128 + i];
        sHold[i] = g_h [(size_t)base4 * 128 + i];
    }
    CP_WAIT0(); __syncthreads();

    int mbase = (wid & 3) * 32, nbase = (wid >> 2) * 64;
    int g = lane >> 2, t = lane & 3;
    float acc[2][8][4];

    // GEMM1: he @ W1q3
    zacc(acc);
    cta_gemm<16>(sAu, sB0u, lane, mbase, nbase, acc);
    __syncthreads();
    cpa_tile<16>(sB0u, g_Wt + (size_t)(wbase + 5) * 16384, tid);   // Lw3 prefetch
    CP_COMMIT();

    // epilogue1: relu(D + P1[node] + P23[gather]) -> sA (rounded)
    #pragma unroll
    for (int mt = 0; mt < 2; ++mt) {
        int r0 = mbase + mt * 16 + g, r1 = r0 + 8;
        const float* p23a = g_P23 + (size_t)sGidx[r0] * 128;
        const float* p23b = g_P23 + (size_t)sGidx[r1] * 128;
        const float* p1a = sP1 + ((r0 >> 5) << 7);
        const float* p1b = sP1 + ((r1 >> 5) << 7);
        #pragma unroll
        for (int nt = 0; nt < 8; ++nt) {
            int c0 = nbase + nt * 8 + t * 2;
            float* d = acc[mt][nt];
            float2 qa = *(const float2*)(p23a + c0);
            float2 qb = *(const float2*)(p23b + c0);
            float2 o0, o1;
            o0.x = ttf(fmaxf(d[0] + qa.x + p1a[c0], 0.f));
            o0.y = ttf(fmaxf(d[1] + qa.y + p1a[c0 + 1], 0.f));
            o1.x = ttf(fmaxf(d[2] + qb.x + p1b[c0], 0.f));
            o1.y = ttf(fmaxf(d[3] + qb.y + p1b[c0 + 1], 0.f));
            *(float2*)(sA + swz<128>(r0, c0)) = o0;
            *(float2*)(sA + swz<128>(r1, c0)) = o1;
        }
    }
    CP_WAIT0(); __syncthreads();

    // GEMM2: m1 @ Lw2
    zacc(acc);
    cta_gemm<16>(sAu, sB1u, lane, mbase, nbase, acc);
    __syncthreads();

    // epilogue2: relu(D + b2) -> sA (rounded)
    #pragma unroll
    for (int mt = 0; mt < 2; ++mt) {
        int r0 = mbase + mt * 16 + g, r1 = r0 + 8;
        #pragma unroll
        for (int nt = 0; nt < 8; ++nt) {
            int c0 = nbase + nt * 8 + t * 2;
            float* d = acc[mt][nt];
            float2 o0, o1;
            o0.x = ttf(fmaxf(d[0] + sBb2[c0], 0.f));
            o0.y = ttf(fmaxf(d[1] + sBb2[c0 + 1], 0.f));
            o1.x = ttf(fmaxf(d[2] + sBb2[c0], 0.f));
            o1.y = ttf(fmaxf(d[3] + sBb2[c0 + 1], 0.f));
            *(float2*)(sA + swz<128>(r0, c0)) = o0;
            *(float2*)(sA + swz<128>(r1, c0)) = o1;
        }
    }
    __syncthreads();

    // GEMM3: m2 @ Lw3
    zacc(acc);
    cta_gemm<16>(sAu, sB0u, lane, mbase, nbase, acc);
    __syncthreads();

    // epilogue3: (D + b3) * vmask -> sB1 rotated row-major
    #pragma unroll
    for (int mt = 0; mt < 2; ++mt) {
        int r0 = mbase + mt * 16 + g, r1 = r0 + 8;
        float v0 = sVm[r0], v1 = sVm[r1];
        #pragma unroll
        for (int nt = 0; nt < 8; ++nt) {
            int c0 = nbase + nt * 8 + t * 2;
            float* d = acc[mt][nt];
            sB1[r0 * 128 + ((c0 + r0) & 127)]     = (d[0] + sBb3[c0]) * v0;
            sB1[r0 * 128 + ((c0 + 1 + r0) & 127)] = (d[1] + sBb3[c0 + 1]) * v0;
            sB1[r1 * 128 + ((c0 + r1) & 127)]     = (d[2] + sBb3[c0]) * v1;
            sB1[r1 * 128 + ((c0 + 1 + r1) & 127)] = (d[3] + sBb3[c0 + 1]) * v1;
        }
    }
    __syncthreads();

    // segment sum over K=32 edges per node
    for (int p = tid; p < 512; p += 256) {
        int gq = p >> 7, j = p & 127, rb = gq * 32;
        float s = 0.f;
        #pragma unroll
        for (int rr = 0; rr < 32; ++rr)
            s += sB1[(rb + rr) * 128 + ((j + rb + rr) & 127)];
        sDh[p] = s * (1.f / 30.f);
    }
    __syncthreads();

    // residual + LN(ddof=1) + mask
    if (tid < 128) {
        int w = tid >> 5, l = tid & 31;
        int nd = base4 + w;
        float x[4], sum = 0.f;
        #pragma unroll
        for (int c = 0; c < 4; ++c) {
            int j = l + 32 * c;
            x[c] = sHold[w * 128 + j] + sDh[w * 128 + j];
            sum += x[c];
        }
        #pragma unroll
        for (int o = 16; o; o >>= 1) sum += __shfl_xor_sync(0xffffffffu, sum, o);
        float mu = sum * (1.f / 128.f);
        float ss = 0.f;
        #pragma unroll
        for (int c = 0; c < 4; ++c) { float dd = x[c] - mu; ss += dd * dd; }
        #pragma unroll
        for (int o = 16; o; o >>= 1) ss += __shfl_xor_sync(0xffffffffu, ss, o);
        float inv = 1.f / (sqrtf(ss * (1.f / 127.f)) + 1e-6f);
        float mk = mask[nd];
        #pragma unroll
        for (int c = 0; c < 4; ++c) {
            int j = l + 32 * c;
            float v = (Lng[layer * 128 + j] * (x[c] - mu) * inv + Lnb[layer * 128 + j]) * mk;
            if (last) {
                outp[(size_t)nd * 128 + j] = v;
            } else {
                g_h [(size_t)nd * 128 + j] = v;
                g_hr[(size_t)nd * 128 + j] = ttf(v);
            }
        }
    }
}

// ---------------- launch ----------------
extern "C" void kernel_launch(void* const* d_in, const int* in_sizes, int n_in,
                              void* d_out, int out_size) {
    const float* V     = (const float*)d_in[0];
    const float* E     = (const float*)d_in[1];
    const float* hS    = (const float*)d_in[2];
    const int*   E_idx = (const int*)  d_in[3];
    const float* mask  = (const float*)d_in[4];
    const float* Wv_w  = (const float*)d_in[5];
    const float* Wv_b  = (const float*)d_in[6];
    const float* Wv_g  = (const float*)d_in[7];
    const float* Wv_b2 = (const float*)d_in[8];
    const float* We_w  = (const float*)d_in[9];
    const float* We_b  = (const float*)d_in[10];
    const float* We_g  = (const float*)d_in[11];
    const float* We_b2 = (const float*)d_in[12];
    const float* Lw1   = (const float*)d_in[13];
    const float* Lb1   = (const float*)d_in[14];
    const float* Lw2   = (const float*)d_in[15];
    const float* Lb2   = (const float*)d_in[16];
    const float* Lw3   = (const float*)d_in[17];
    const float* Lb3   = (const float*)d_in[18];
    const float* Ln_g  = (const float*)d_in[19];
    const float* Ln_b  = (const float*)d_in[20];
    float* out = (float*)d_out;

    cudaFuncSetAttribute(embed_k<64, 0>, cudaFuncAttributeMaxDynamicSharedMemorySize, SM_EMB);
    cudaFuncSetAttribute(embed_k<48, 1>, cudaFuncAttributeMaxDynamicSharedMemorySize, SM_EMB);
    cudaFuncSetAttribute(node_proj_k,    cudaFuncAttributeMaxDynamicSharedMemorySize, SM_PROJ);
    cudaFuncSetAttribute(edge_layer_k,   cudaFuncAttributeMaxDynamicSharedMemorySize, SM_EDGE);

    pack_w<<<20, 256>>>(Wv_w, We_w, Lw1, Lw2, Lw3);
    pack_hs<<<128, 256>>>(hS);
    embed_k<64, 0><<<32,   256, SM_EMB>>>(V, Wv_b, Wv_g, Wv_b2, 0);
    embed_k<48, 1><<<1024, 256, SM_EMB>>>(E, We_b, We_g, We_b2, 1);

    for (int layer = 0; layer < 3; ++layer) {
        node_proj_k<<<dim3(32, 2), 256, SM_PROJ>>>(Lb1, layer);
        edge_layer_k<<<1024, 256, SM_EDGE>>>(E_idx, mask, Lb2, Lb3, Ln_g, Ln_b,
                                             layer, layer == 2 ? 1 : 0, out);
    }
}

// round 5
// speedup vs baseline: 3.6888x; 1.0990x over previous
#include <cuda_runtime.h>
#include <cstdint>
#include <math.h>

#define NODES 4096
#define EDGES 131072

// ---------------- device scratch (static globals) ----------------
__device__ float g_her[EDGES * 128];  // tf32-rounded edge embeddings, row-major
__device__ float g_h  [NODES * 128];  // exact node state
__device__ float g_hr [NODES * 128];  // tf32-rounded node state
__device__ float g_hSr[NODES * 128];  // tf32-rounded hS
__device__ float g_P1 [NODES * 128];
__device__ float g_P23[NODES * 128];
__device__ float g_Wt [20 * 16384];   // weights as Bt[n][k], tf32-rounded

// ---------------- helpers ----------------
__device__ __forceinline__ uint32_t s2u(const void* p) {
    uint32_t a;
    asm("{ .reg .u64 t; cvta.to.shared.u64 t, %1; cvt.u32.u64 %0, t; }" : "=r"(a) : "l"(p));
    return a;
}
__device__ __forceinline__ float ttf(float x) {   // round f32 -> tf32 (rna)
    uint32_t u;
    asm("cvt.rna.tf32.f32 %0, %1;" : "=r"(u) : "f"(x));
    return __uint_as_float(u);
}
__device__ __forceinline__ void ldsm4(uint32_t d[4], uint32_t a) {
    asm volatile("ldmatrix.sync.aligned.m8n8.x4.shared.b16 {%0,%1,%2,%3}, [%4];"
                 : "=r"(d[0]), "=r"(d[1]), "=r"(d[2]), "=r"(d[3]) : "r"(a));
}
__device__ __forceinline__ void mma8(float d[4], const uint32_t a[4], uint32_t b0, uint32_t b1) {
    asm volatile("mma.sync.aligned.m16n8k8.row.col.f32.tf32.tf32.f32 "
                 "{%0,%1,%2,%3}, {%4,%5,%6,%7}, {%8,%9}, {%0,%1,%2,%3};"
                 : "+f"(d[0]), "+f"(d[1]), "+f"(d[2]), "+f"(d[3])
                 : "r"(a[0]), "r"(a[1]), "r"(a[2]), "r"(a[3]), "r"(b0), "r"(b1));
}
#define CP16(dst, src) asm volatile("cp.async.cg.shared.global [%0], [%1], 16;" :: "r"(dst), "l"(src))
#define CP_COMMIT()    asm volatile("cp.async.commit_group;")
#define CP_WAIT0()     asm volatile("cp.async.wait_group 0;" ::: "memory")

// swizzled float index within a 128 x ROWF tile (XOR on 16B granules)
template <int ROWF>
__device__ __forceinline__ int swz(int r, int c) { return r * ROWF + (c ^ ((r & 7) << 2)); }

// cp.async copy of a 128 x (KSTEPS*8) f32 tile, row-major contiguous src
template <int KSTEPS>
__device__ __forceinline__ void cpa_tile(uint32_t sDst, const float* __restrict__ g, int tid) {
    const int ROWF = KSTEPS * 8;
    const int NF4 = 128 * ROWF / 4;
    #pragma unroll 4
    for (int i = tid; i < NF4; i += 256) {
        int r = i / (ROWF / 4), c = (i % (ROWF / 4)) * 4;
        CP16(sDst + (swz<ROWF>(r, c) << 2), g + i * 4);
    }
}

__device__ __forceinline__ void zacc(float acc[2][8][4]) {
    #pragma unroll
    for (int i = 0; i < 2; ++i)
        #pragma unroll
        for (int j = 0; j < 8; ++j)
            #pragma unroll
            for (int k = 0; k < 4; ++k) acc[i][j][k] = 0.f;
}

// non-pipelined CTA GEMM (low regs, for embed): D += A[128,K] @ Bt[128,K]^T
template <int KSTEPS>
__device__ __forceinline__ void cta_gemm_np(uint32_t sAu, uint32_t sBu, int lane,
                                            int mbase, int nbase, float acc[2][8][4]) {
    const int ROWF = KSTEPS * 8;
    int ar = lane & 15, ac = (lane >> 4) << 2;
    int br = (lane & 7) + ((lane >> 4) << 3), bc = (lane & 8) ? 4 : 0;
    #pragma unroll
    for (int k0 = 0; k0 < KSTEPS; ++k0) {
        uint32_t a[2][4];
        #pragma unroll
        for (int mt = 0; mt < 2; ++mt)
            ldsm4(a[mt], sAu + (swz<ROWF>(mbase + mt * 16 + ar, k0 * 8 + ac) << 2));
        #pragma unroll
        for (int q = 0; q < 4; ++q) {
            uint32_t b[4];
            ldsm4(b, sBu + (swz<ROWF>(nbase + q * 16 + br, k0 * 8 + bc) << 2));
            mma8(acc[0][q * 2],     a[0], b[0], b[1]);
            mma8(acc[0][q * 2 + 1], a[0], b[2], b[3]);
            mma8(acc[1][q * 2],     a[1], b[0], b[1]);
            mma8(acc[1][q * 2 + 1], a[1], b[2], b[3]);
        }
    }
}

// pipelined CTA GEMM (register double-buffered LDSM, for proj/edge)
template <int KSTEPS>
__device__ __forceinline__ void cta_gemm_pl(uint32_t sAu, uint32_t sBu, int lane,
                                            int mbase, int nbase, float acc[2][8][4]) {
    const int ROWF = KSTEPS * 8;
    int ar = lane & 15, ac = (lane >> 4) << 2;
    int br = (lane & 7) + ((lane >> 4) << 3), bc = (lane & 8) ? 4 : 0;
    uint32_t a[2][2][4], b[2][4][4];
    ldsm4(a[0][0], sAu + (swz<ROWF>(mbase + ar, ac) << 2));
    ldsm4(a[0][1], sAu + (swz<ROWF>(mbase + 16 + ar, ac) << 2));
    #pragma unroll
    for (int q = 0; q < 4; ++q)
        ldsm4(b[0][q], sBu + (swz<ROWF>(nbase + q * 16 + br, bc) << 2));
    #pragma unroll
    for (int k0 = 0; k0 < KSTEPS; ++k0) {
        const int cur = k0 & 1, nxt = cur ^ 1;
        if (k0 + 1 < KSTEPS) {
            int c = (k0 + 1) * 8;
            ldsm4(a[nxt][0], sAu + (swz<ROWF>(mbase + ar, c + ac) << 2));
            ldsm4(a[nxt][1], sAu + (swz<ROWF>(mbase + 16 + ar, c + ac) << 2));
            #pragma unroll
            for (int q = 0; q < 4; ++q)
                ldsm4(b[nxt][q], sBu + (swz<ROWF>(nbase + q * 16 + br, c + bc) << 2));
        }
        #pragma unroll
        for (int q = 0; q < 4; ++q) {
            mma8(acc[0][q * 2],     a[cur][0], b[cur][q][0], b[cur][q][1]);
            mma8(acc[0][q * 2 + 1], a[cur][0], b[cur][q][2], b[cur][q][3]);
            mma8(acc[1][q * 2],     a[cur][1], b[cur][q][0], b[cur][q][1]);
            mma8(acc[1][q * 2 + 1], a[cur][1], b[cur][q][2], b[cur][q][3]);
        }
    }
}

// ---------------- pack: weights -> Bt[n][k] tf32 ----------------
__global__ void pack_w(const float* __restrict__ Wv, const float* __restrict__ We,
                       const float* __restrict__ Lw1, const float* __restrict__ Lw2,
                       const float* __restrict__ Lw3) {
    int m = blockIdx.x;
    const float* src; int Kin, ROWF;
    if (m == 0)      { src = Wv; Kin = 64; ROWF = 64; }
    else if (m == 1) { src = We; Kin = 48; ROWF = 64; }
    else {
        int l = (m - 2) / 6, q = (m - 2) % 6;
        if (q < 4)       src = Lw1 + ((size_t)l * 512 + q * 128) * 128;
        else if (q == 4) src = Lw2 + (size_t)l * 16384;
        else             src = Lw3 + (size_t)l * 16384;
        Kin = 128; ROWF = 128;
    }
    float* dst = g_Wt + (size_t)m * 16384;
    int tot = 128 * ROWF;
    for (int i = threadIdx.x; i < tot; i += blockDim.x) {
        int n = i / ROWF, k = i % ROWF;
        dst[i] = (k < Kin) ? ttf(src[(size_t)k * 128 + n]) : 0.f;
    }
}
__global__ void pack_hs(const float* __restrict__ hS) {
    for (int i = blockIdx.x * blockDim.x + threadIdx.x; i < NODES * 128;
         i += gridDim.x * blockDim.x)
        g_hSr[i] = ttf(hS[i]);
}

// ---------------- embed: norm(X@W + b), LN from accumulator registers -------
// smem floats: sA 0(8192) sW 8192(8192) sBias 16384 sG 16512 sB2 16640
//              sRS 16768(256) sRQ 17024(256) -> 17280 floats (69 KB, 2 CTAs/SM)
#define SM_EMB (17280 * 4)
template <int KIN, int MODE>  // MODE 0: node (g_h + g_hr), 1: edge (g_her)
__global__ void __launch_bounds__(256, 2)
embed_k(const float* __restrict__ X, const float* __restrict__ bb,
        const float* __restrict__ gg, const float* __restrict__ b2, int wslot) {
    extern __shared__ float sm[];
    float* sA = sm; float* sW = sm + 8192;
    float* sBias = sm + 16384; float* sG = sm + 16512; float* sB2 = sm + 16640;
    float* sRS = sm + 16768; float* sRQ = sm + 17024;
    uint32_t sAu = s2u(sA), sWu = s2u(sW);
    int tid = threadIdx.x, lane = tid & 31, wid = tid >> 5, blk = blockIdx.x;

    cpa_tile<8>(sWu, g_Wt + (size_t)wslot * 16384, tid);
    CP_COMMIT();
    for (int i = tid; i < 2048; i += 256) {
        int r = i >> 4, c4 = i & 15;
        float4 v;
        if (c4 * 4 < KIN) {
            v = *(const float4*)(X + ((size_t)blk * 128 + r) * KIN + c4 * 4);
            v.x = ttf(v.x); v.y = ttf(v.y); v.z = ttf(v.z); v.w = ttf(v.w);
        } else v = make_float4(0.f, 0.f, 0.f, 0.f);
        *(float4*)(sA + swz<64>(r, c4 * 4)) = v;
    }
    if (tid < 128) { sBias[tid] = bb[tid]; sG[tid] = gg[tid]; sB2[tid] = b2[tid]; }
    CP_WAIT0(); __syncthreads();

    float acc[2][8][4];
    zacc(acc);
    int mbase = (wid & 3) * 32, nbase = (wid >> 2) * 64;
    cta_gemm_np<8>(sAu, sWu, lane, mbase, nbase, acc);

    // add bias; per-row partial sum / sumsq straight from registers
    int g = lane >> 2, t = lane & 3;
    float p[4] = {0.f, 0.f, 0.f, 0.f}, q[4] = {0.f, 0.f, 0.f, 0.f};
    #pragma unroll
    for (int mt = 0; mt < 2; ++mt)
        #pragma unroll
        for (int nt = 0; nt < 8; ++nt) {
            int c0 = nbase + nt * 8 + t * 2;
            float* d = acc[mt][nt];
            d[0] += sBias[c0]; d[1] += sBias[c0 + 1];
            d[2] += sBias[c0]; d[3] += sBias[c0 + 1];
            p[mt * 2]     += d[0] + d[1];  q[mt * 2]     += d[0] * d[0] + d[1] * d[1];
            p[mt * 2 + 1] += d[2] + d[3];  q[mt * 2 + 1] += d[2] * d[2] + d[3] * d[3];
        }
    #pragma unroll
    for (int i = 0; i < 4; ++i) {
        p[i] += __shfl_xor_sync(0xffffffffu, p[i], 1);
        p[i] += __shfl_xor_sync(0xffffffffu, p[i], 2);
        q[i] += __shfl_xor_sync(0xffffffffu, q[i], 1);
        q[i] += __shfl_xor_sync(0xffffffffu, q[i], 2);
    }
    int half = nbase >> 6;
    if (t == 0) {
        #pragma unroll
        for (int i = 0; i < 4; ++i) {
            int r = mbase + (i >> 1) * 16 + (i & 1) * 8 + g;
            sRS[r * 2 + half] = p[i];
            sRQ[r * 2 + half] = q[i];
        }
    }
    __syncthreads();

    #pragma unroll
    for (int mt = 0; mt < 2; ++mt)
        #pragma unroll
        for (int jj = 0; jj < 2; ++jj) {
            int r = mbase + mt * 16 + jj * 8 + g;
            float mu = (sRS[r * 2] + sRS[r * 2 + 1]) * (1.f / 128.f);
            float qq = sRQ[r * 2] + sRQ[r * 2 + 1];
            float var = (qq - 128.f * mu * mu) * (1.f / 127.f);
            float inv = 1.f / (sqrtf(fmaxf(var, 0.f)) + 1e-6f);
            #pragma unroll
            for (int nt = 0; nt < 8; ++nt) {
                int c0 = nbase + nt * 8 + t * 2;
                float* d = acc[mt][nt];
                float v0 = sG[c0]     * (d[jj * 2]     - mu) * inv + sB2[c0];
                float v1 = sG[c0 + 1] * (d[jj * 2 + 1] - mu) * inv + sB2[c0 + 1];
                size_t off = ((size_t)blk * 128 + r) * 128 + c0;
                if (MODE == 0) {
                    *(float2*)(g_h + off)  = make_float2(v0, v1);
                    *(float2*)(g_hr + off) = make_float2(ttf(v0), ttf(v1));
                } else {
                    *(float2*)(g_her + off) = make_float2(ttf(v0), ttf(v1));
                }
            }
        }
}

// ---------------- node projections ----------------
// y==0: P1 = h@W1q0 + b1 ; y==1: P23 = h@W1q1 + hS@W1q2
#define SM_PROJ (49280 * 4)
__global__ void __launch_bounds__(256, 1)
node_proj_k(const float* __restrict__ Lb1, int layer) {
    extern __shared__ float sm[];
    float* sA = sm; float* sW0 = sm + 16384; float* sW1 = sm + 32768;
    float* sBias = sm + 49152;
    uint32_t sAu = s2u(sA), sW0u = s2u(sW0), sW1u = s2u(sW1);
    int tid = threadIdx.x, lane = tid & 31, wid = tid >> 5;
    int blk = blockIdx.x, which = blockIdx.y;
    int wbase = 2 + layer * 6;

    cpa_tile<16>(sAu, g_hr + (size_t)blk * 16384, tid);
    cpa_tile<16>(sW0u, g_Wt + (size_t)(wbase + (which ? 1 : 0)) * 16384, tid);
    if (which) cpa_tile<16>(sW1u, g_Wt + (size_t)(wbase + 2) * 16384, tid);
    CP_COMMIT();
    if (tid < 128) sBias[tid] = which ? 0.f : Lb1[layer * 128 + tid];
    CP_WAIT0(); __syncthreads();

    float acc[2][8][4];
    zacc(acc);
    int mbase = (wid & 3) * 32, nbase = (wid >> 2) * 64;
    cta_gemm_pl<16>(sAu, sW0u, lane, mbase, nbase, acc);

    if (which) {
        __syncthreads();
        cpa_tile<16>(sAu, g_hSr + (size_t)blk * 16384, tid);
        CP_COMMIT(); CP_WAIT0(); __syncthreads();
        cta_gemm_pl<16>(sAu, sW1u, lane, mbase, nbase, acc);
    }

    float* out = which ? g_P23 : g_P1;
    int g = lane >> 2, t = lane & 3;
    #pragma unroll
    for (int mt = 0; mt < 2; ++mt) {
        int r0 = mbase + mt * 16 + g;
        #pragma unroll
        for (int nt = 0; nt < 8; ++nt) {
            int c0 = nbase + nt * 8 + t * 2;
            float* d = acc[mt][nt];
            float2 o0 = make_float2(d[0] + sBias[c0], d[1] + sBias[c0 + 1]);
            float2 o1 = make_float2(d[2] + sBias[c0], d[3] + sBias[c0 + 1]);
            *(float2*)(out + ((size_t)blk * 128 + r0) * 128 + c0) = o0;
            *(float2*)(out + ((size_t)blk * 128 + r0 + 8) * 128 + c0) = o1;
        }
    }
}

// ---------------- fused edge layer ----------------
// smem floats: sA 0(16384) sB0 16384 sB1 32768 sP1 49152(512) sHold 49664(512)
// sDh 50176(512) sVm 50688(128) sBb2 50816(128) sBb3 50944(128) sGidx 51072(128)
#define SM_EDGE (51200 * 4)
__global__ void __launch_bounds__(256, 1)
edge_layer_k(const int* __restrict__ Eidx, const float* __restrict__ mask,
             const float* __restrict__ Lb2, const float* __restrict__ Lb3,
             const float* __restrict__ Lng, const float* __restrict__ Lnb,
             int layer, int last, float* __restrict__ outp) {
    extern __shared__ float sm[];
    float* sA = sm; float* sB0 = sm + 16384; float* sB1 = sm + 32768;
    float* sP1 = sm + 49152; float* sHold = sm + 49664; float* sDh = sm + 50176;
    float* sVm = sm + 50688; float* sBb2 = sm + 50816; float* sBb3 = sm + 50944;
    int* sGidx = (int*)(sm + 51072);
    uint32_t sAu = s2u(sA), sB0u = s2u(sB0), sB1u = s2u(sB1);

    int tid = threadIdx.x, lane = tid & 31, wid = tid >> 5, blk = blockIdx.x;
    int base4 = blk * 4;
    int wbase = 2 + layer * 6;

    cpa_tile<16>(sAu, g_her + (size_t)blk * 16384, tid);
    cpa_tile<16>(sB0u, g_Wt + (size_t)(wbase + 3) * 16384, tid);   // W1q3 (he)
    cpa_tile<16>(sB1u, g_Wt + (size_t)(wbase + 4) * 16384, tid);   // Lw2
    CP_COMMIT();

    if (tid < 128) {
        int nd = base4 + (tid >> 5);
        int idx = Eidx[nd * 32 + (tid & 31)];
        int gi = ((nd >> 11) << 11) + idx;
        sGidx[tid] = gi;
        sVm[tid] = mask[gi];
        sBb2[tid] = Lb2[layer * 128 + tid];
        sBb3[tid] = Lb3[layer * 128 + tid];
    }
    for (int i = tid; i < 512; i += 256) {
        sP1[i]   = g_P1[(size_t)base4 * 128 + i];
        sHold[i] = g_h [(size_t)base4 * 128 + i];
    }
    CP_WAIT0(); __syncthreads();

    int mbase = (wid & 3) * 32, nbase = (wid >> 2) * 64;
    int g = lane >> 2, t = lane & 3;
    float acc[2][8][4];

    // GEMM1: he @ W1q3
    zacc(acc);
    cta_gemm_pl<16>(sAu, sB0u, lane, mbase, nbase, acc);
    __syncthreads();
    cpa_tile<16>(sB0u, g_Wt + (size_t)(wbase + 5) * 16384, tid);   // Lw3 prefetch
    CP_COMMIT();

    // epilogue1: relu(D + P1[node] + P23[gather]) -> sA (rounded)
    #pragma unroll
    for (int mt = 0; mt < 2; ++mt) {
        int r0 = mbase + mt * 16 + g, r1 = r0 + 8;
        const float* p23a = g_P23 + (size_t)sGidx[r0] * 128;
        const float* p23b = g_P23 + (size_t)sGidx[r1] * 128;
        const float* p1a = sP1 + ((r0 >> 5) << 7);
        const float* p1b = sP1 + ((r1 >> 5) << 7);
        #pragma unroll
        for (int nt = 0; nt < 8; ++nt) {
            int c0 = nbase + nt * 8 + t * 2;
            float* d = acc[mt][nt];
            float2 qa = *(const float2*)(p23a + c0);
            float2 qb = *(const float2*)(p23b + c0);
            float2 o0, o1;
            o0.x = ttf(fmaxf(d[0] + qa.x + p1a[c0], 0.f));
            o0.y = ttf(fmaxf(d[1] + qa.y + p1a[c0 + 1], 0.f));
            o1.x = ttf(fmaxf(d[2] + qb.x + p1b[c0], 0.f));
            o1.y = ttf(fmaxf(d[3] + qb.y + p1b[c0 + 1], 0.f));
            *(float2*)(sA + swz<128>(r0, c0)) = o0;
            *(float2*)(sA + swz<128>(r1, c0)) = o1;
        }
    }
    CP_WAIT0(); __syncthreads();

    // GEMM2: m1 @ Lw2
    zacc(acc);
    cta_gemm_pl<16>(sAu, sB1u, lane, mbase, nbase, acc);
    __syncthreads();

    // epilogue2: relu(D + b2) -> sA (rounded)
    #pragma unroll
    for (int mt = 0; mt < 2; ++mt) {
        int r0 = mbase + mt * 16 + g, r1 = r0 + 8;
        #pragma unroll
        for (int nt = 0; nt < 8; ++nt) {
            int c0 = nbase + nt * 8 + t * 2;
            float* d = acc[mt][nt];
            float2 o0, o1;
            o0.x = ttf(fmaxf(d[0] + sBb2[c0], 0.f));
            o0.y = ttf(fmaxf(d[1] + sBb2[c0 + 1], 0.f));
            o1.x = ttf(fmaxf(d[2] + sBb2[c0], 0.f));
            o1.y = ttf(fmaxf(d[3] + sBb2[c0 + 1], 0.f));
            *(float2*)(sA + swz<128>(r0, c0)) = o0;
            *(float2*)(sA + swz<128>(r1, c0)) = o1;
        }
    }
    __syncthreads();

    // GEMM3: m2 @ Lw3
    zacc(acc);
    cta_gemm_pl<16>(sAu, sB0u, lane, mbase, nbase, acc);
    __syncthreads();

    // epilogue3: (D + b3) * vmask -> sB1 rotated row-major
    #pragma unroll
    for (int mt = 0; mt < 2; ++mt) {
        int r0 = mbase + mt * 16 + g, r1 = r0 + 8;
        float v0 = sVm[r0], v1 = sVm[r1];
        #pragma unroll
        for (int nt = 0; nt < 8; ++nt) {
            int c0 = nbase + nt * 8 + t * 2;
            float* d = acc[mt][nt];
            sB1[r0 * 128 + ((c0 + r0) & 127)]     = (d[0] + sBb3[c0]) * v0;
            sB1[r0 * 128 + ((c0 + 1 + r0) & 127)] = (d[1] + sBb3[c0 + 1]) * v0;
            sB1[r1 * 128 + ((c0 + r1) & 127)]     = (d[2] + sBb3[c0]) * v1;
            sB1[r1 * 128 + ((c0 + 1 + r1) & 127)] = (d[3] + sBb3[c0 + 1]) * v1;
        }
    }
    __syncthreads();

    // segment sum over K=32 edges per node
    for (int p = tid; p < 512; p += 256) {
        int gq = p >> 7, j = p & 127, rb = gq * 32;
        float s = 0.f;
        #pragma unroll
        for (int rr = 0; rr < 32; ++rr)
            s += sB1[(rb + rr) * 128 + ((j + rb + rr) & 127)];
        sDh[p] = s * (1.f / 30.f);
    }
    __syncthreads();

    // residual + LN(ddof=1) + mask
    if (tid < 128) {
        int w = tid >> 5, l = tid & 31;
        int nd = base4 + w;
        float x[4], sum = 0.f;
        #pragma unroll
        for (int c = 0; c < 4; ++c) {
            int j = l + 32 * c;
            x[c] = sHold[w * 128 + j] + sDh[w * 128 + j];
            sum += x[c];
        }
        #pragma unroll
        for (int o = 16; o; o >>= 1) sum += __shfl_xor_sync(0xffffffffu, sum, o);
        float mu = sum * (1.f / 128.f);
        float ss = 0.f;
        #pragma unroll
        for (int c = 0; c < 4; ++c) { float dd = x[c] - mu; ss += dd * dd; }
        #pragma unroll
        for (int o = 16; o; o >>= 1) ss += __shfl_xor_sync(0xffffffffu, ss, o);
        float inv = 1.f / (sqrtf(ss * (1.f / 127.f)) + 1e-6f);
        float mk = mask[nd];
        #pragma unroll
        for (int c = 0; c < 4; ++c) {
            int j = l + 32 * c;
            float v = (Lng[layer * 128 + j] * (x[c] - mu) * inv + Lnb[layer * 128 + j]) * mk;
            if (last) {
                outp[(size_t)nd * 128 + j] = v;
            } else {
                g_h [(size_t)nd * 128 + j] = v;
                g_hr[(size_t)nd * 128 + j] = ttf(v);
            }
        }
    }
}

// ---------------- launch ----------------
extern "C" void kernel_launch(void* const* d_in, const int* in_sizes, int n_in,
                              void* d_out, int out_size) {
    const float* V     = (const float*)d_in[0];
    const float* E     = (const float*)d_in[1];
    const float* hS    = (const float*)d_in[2];
    const int*   E_idx = (const int*)  d_in[3];
    const float* mask  = (const float*)d_in[4];
    const float* Wv_w  = (const float*)d_in[5];
    const float* Wv_b  = (const float*)d_in[6];
    const float* Wv_g  = (const float*)d_in[7];
    const float* Wv_b2 = (const float*)d_in[8];
    const float* We_w  = (const float*)d_in[9];
    const float* We_b  = (const float*)d_in[10];
    const float* We_g  = (const float*)d_in[11];
    const float* We_b2 = (const float*)d_in[12];
    const float* Lw1   = (const float*)d_in[13];
    const float* Lb1   = (const float*)d_in[14];
    const float* Lw2   = (const float*)d_in[15];
    const float* Lb2   = (const float*)d_in[16];
    const float* Lw3   = (const float*)d_in[17];
    const float* Lb3   = (const float*)d_in[18];
    const float* Ln_g  = (const float*)d_in[19];
    const float* Ln_b  = (const float*)d_in[20];
    float* out = (float*)d_out;

    cudaFuncSetAttribute(embed_k<64, 0>, cudaFuncAttributeMaxDynamicSharedMemorySize, SM_EMB);
    cudaFuncSetAttribute(embed_k<48, 1>, cudaFuncAttributeMaxDynamicSharedMemorySize, SM_EMB);
    cudaFuncSetAttribute(node_proj_k,    cudaFuncAttributeMaxDynamicSharedMemorySize, SM_PROJ);
    cudaFuncSetAttribute(edge_layer_k,   cudaFuncAttributeMaxDynamicSharedMemorySize, SM_EDGE);

    pack_w<<<20, 256>>>(Wv_w, We_w, Lw1, Lw2, Lw3);
    pack_hs<<<128, 256>>>(hS);
    embed_k<64, 0><<<32,   256, SM_EMB>>>(V, Wv_b, Wv_g, Wv_b2, 0);
    embed_k<48, 1><<<1024, 256, SM_EMB>>>(E, We_b, We_g, We_b2, 1);

    for (int layer = 0; layer < 3; ++layer) {
        node_proj_k<<<dim3(32, 2), 256, SM_PROJ>>>(Lb1, layer);
        edge_layer_k<<<1024, 256, SM_EDGE>>>(E_idx, mask, Lb2, Lb3, Ln_g, Ln_b,
                                             layer, layer == 2 ? 1 : 0, out);
    }
}

// round 6
// speedup vs baseline: 6.6322x; 1.7980x over previous
#include <cuda_runtime.h>
#include <cuda_fp16.h>
#include <cstdint>
#include <math.h>

#define NODES 4096
#define EDGES 131072

// ---------------- device scratch (static globals) ----------------
__device__ __align__(256) __half g_her[EDGES * 128];  // fp16 edge embeddings
__device__ __align__(256) float  g_h  [NODES * 128];  // exact node state
__device__ __align__(256) __half g_hr [NODES * 128];  // fp16 node state
__device__ __align__(256) __half g_hSr[NODES * 128];  // fp16 hS
__device__ __align__(256) float  g_P1 [NODES * 128];
__device__ __align__(256) float  g_P23[NODES * 128];
__device__ __align__(256) __half g_Wt [20 * 16384];   // weights Bt[n][k] fp16

// ---------------- helpers ----------------
__device__ __forceinline__ uint32_t s2u(const void* p) {
    uint32_t a;
    asm("{ .reg .u64 t; cvta.to.shared.u64 t, %1; cvt.u32.u64 %0, t; }" : "=r"(a) : "l"(p));
    return a;
}
__device__ __forceinline__ uint32_t f2h2(float x, float y) {
    __half2 h = __floats2half2_rn(x, y);
    return *(uint32_t*)&h;
}
__device__ __forceinline__ void ldsm4(uint32_t d[4], uint32_t a) {
    asm volatile("ldmatrix.sync.aligned.m8n8.x4.shared.b16 {%0,%1,%2,%3}, [%4];"
                 : "=r"(d[0]), "=r"(d[1]), "=r"(d[2]), "=r"(d[3]) : "r"(a));
}
__device__ __forceinline__ void mma16(float d[4], const uint32_t a[4], uint32_t b0, uint32_t b1) {
    asm volatile("mma.sync.aligned.m16n8k16.row.col.f32.f16.f16.f32 "
                 "{%0,%1,%2,%3}, {%4,%5,%6,%7}, {%8,%9}, {%0,%1,%2,%3};"
                 : "+f"(d[0]), "+f"(d[1]), "+f"(d[2]), "+f"(d[3])
                 : "r"(a[0]), "r"(a[1]), "r"(a[2]), "r"(a[3]), "r"(b0), "r"(b1));
}
#define CP16(dst, src) asm volatile("cp.async.cg.shared.global [%0], [%1], 16;" :: "r"(dst), "l"(src))
#define CP_COMMIT()    asm volatile("cp.async.commit_group;")
#define CP_WAIT0()     asm volatile("cp.async.wait_group 0;" ::: "memory")

// swizzled HALF index in a 128 x ROWH half tile (XOR granule = 8 halfs = 16B)
template <int ROWH>
__device__ __forceinline__ int swzh(int r, int c) { return r * ROWH + (c ^ ((r & 7) << 3)); }

// cp.async copy of a 128 x ROWH half tile (row-major contiguous src)
template <int ROWH>
__device__ __forceinline__ void cpa_h(uint32_t sDst, const __half* __restrict__ g, int tid) {
    const int NCH = 128 * ROWH / 8;
    #pragma unroll 4
    for (int i = tid; i < NCH; i += 256) {
        int r = i / (ROWH / 8), c = (i % (ROWH / 8)) * 8;
        CP16(sDst + swzh<ROWH>(r, c) * 2, g + (size_t)r * ROWH + c);
    }
}

__device__ __forceinline__ void zacc(float acc[2][8][4]) {
    #pragma unroll
    for (int i = 0; i < 2; ++i)
        #pragma unroll
        for (int j = 0; j < 8; ++j)
            #pragma unroll
            for (int k = 0; k < 4; ++k) acc[i][j][k] = 0.f;
}

// CTA GEMM fp16: D[128,128] += A[128,K] @ Bt[128,K]^T, 8 warps, warp tile 32x64
template <int KH, int ROWH>   // KH = K/16
__device__ __forceinline__ void cta_gemm_h(uint32_t sAu, uint32_t sBu, int lane,
                                           int mbase, int nbase, float acc[2][8][4]) {
    int arow = lane & 15, acol = (lane >> 4) << 3;
    int bn = ((lane >> 4) & 1) * 8 + (lane & 7), bk = ((lane >> 3) & 1) * 8;
    #pragma unroll
    for (int k0 = 0; k0 < KH; ++k0) {
        int kh = k0 * 16;
        uint32_t a0[4], a1[4];
        ldsm4(a0, sAu + swzh<ROWH>(mbase + arow,      kh + acol) * 2);
        ldsm4(a1, sAu + swzh<ROWH>(mbase + 16 + arow, kh + acol) * 2);
        #pragma unroll
        for (int q8 = 0; q8 < 4; ++q8) {
            uint32_t b[4];
            ldsm4(b, sBu + swzh<ROWH>(nbase + q8 * 16 + bn, kh + bk) * 2);
            mma16(acc[0][q8 * 2],     a0, b[0], b[1]);
            mma16(acc[0][q8 * 2 + 1], a0, b[2], b[3]);
            mma16(acc[1][q8 * 2],     a1, b[0], b[1]);
            mma16(acc[1][q8 * 2 + 1], a1, b[2], b[3]);
        }
    }
}

// ---------------- pack: weights -> Bt[n][k] fp16 ----------------
__global__ void pack_w(const float* __restrict__ Wv, const float* __restrict__ We,
                       const float* __restrict__ Lw1, const float* __restrict__ Lw2,
                       const float* __restrict__ Lw3) {
    int m = blockIdx.x;
    const float* src; int Kin, ROWH;
    if (m == 0)      { src = Wv; Kin = 64; ROWH = 64; }
    else if (m == 1) { src = We; Kin = 48; ROWH = 64; }
    else {
        int l = (m - 2) / 6, q = (m - 2) % 6;
        if (q < 4)       src = Lw1 + ((size_t)l * 512 + q * 128) * 128;
        else if (q == 4) src = Lw2 + (size_t)l * 16384;
        else             src = Lw3 + (size_t)l * 16384;
        Kin = 128; ROWH = 128;
    }
    __half* dst = g_Wt + (size_t)m * 16384;
    int tot = 128 * ROWH;
    for (int i = threadIdx.x; i < tot; i += blockDim.x) {
        int n = i / ROWH, k = i % ROWH;
        dst[i] = (k < Kin) ? __float2half_rn(src[(size_t)k * 128 + n]) : __half(0.f);
    }
}
__global__ void pack_hs(const float* __restrict__ hS) {
    for (int i = blockIdx.x * blockDim.x + threadIdx.x; i < NODES * 128;
         i += gridDim.x * blockDim.x)
        g_hSr[i] = __float2half_rn(hS[i]);
}

// ---------------- embed: norm(X@W + b), LN from accumulators ----------------
// halfs: sAh 0(8192) sWh 8192(8192); floats after: bias 128, g 128, b2 128,
// RS 256, RQ 256
#define SM_EMB (2 * 16384 + 896 * 4)
template <int KIN, int MODE>  // MODE 0: node (g_h + g_hr), 1: edge (g_her)
__global__ void __launch_bounds__(256, 2)
embed_k(const float* __restrict__ X, const float* __restrict__ bb,
        const float* __restrict__ gg, const float* __restrict__ b2, int wslot) {
    extern __shared__ __half smh[];
    __half* sAh = smh; __half* sWh = smh + 8192;
    float* fx = (float*)(smh + 16384);
    float* sBias = fx; float* sG = fx + 128; float* sB2 = fx + 256;
    float* sRS = fx + 384; float* sRQ = fx + 640;
    uint32_t sAu = s2u(sAh), sWu = s2u(sWh);
    int tid = threadIdx.x, lane = tid & 31, wid = tid >> 5, blk = blockIdx.x;

    cpa_h<64>(sWu, g_Wt + (size_t)wslot * 16384, tid);
    CP_COMMIT();
    // A: load f32 -> fp16, swizzle-store (zero pad K to 64)
    for (int i = tid; i < 1024; i += 256) {
        int r = i >> 3, gc = (i & 7) * 8;
        uint4 u;
        if (gc < KIN) {
            const float* xp = X + ((size_t)blk * 128 + r) * KIN + gc;
            float4 v0 = *(const float4*)(xp);
            float4 v1 = *(const float4*)(xp + 4);
            u.x = f2h2(v0.x, v0.y); u.y = f2h2(v0.z, v0.w);
            u.z = f2h2(v1.x, v1.y); u.w = f2h2(v1.z, v1.w);
        } else u = make_uint4(0, 0, 0, 0);
        *(uint4*)((char*)sAh + swzh<64>(r, gc) * 2) = u;
    }
    if (tid < 128) { sBias[tid] = bb[tid]; sG[tid] = gg[tid]; sB2[tid] = b2[tid]; }
    CP_WAIT0(); __syncthreads();

    float acc[2][8][4];
    zacc(acc);
    int mbase = (wid & 3) * 32, nbase = (wid >> 2) * 64;
    cta_gemm_h<4, 64>(sAu, sWu, lane, mbase, nbase, acc);

    // bias + per-row sum/sumsq from registers
    int g = lane >> 2, t = lane & 3;
    float p[4] = {0, 0, 0, 0}, q[4] = {0, 0, 0, 0};
    #pragma unroll
    for (int mt = 0; mt < 2; ++mt)
        #pragma unroll
        for (int nt = 0; nt < 8; ++nt) {
            int c0 = nbase + nt * 8 + t * 2;
            float* d = acc[mt][nt];
            d[0] += sBias[c0]; d[1] += sBias[c0 + 1];
            d[2] += sBias[c0]; d[3] += sBias[c0 + 1];
            p[mt * 2]     += d[0] + d[1];  q[mt * 2]     += d[0] * d[0] + d[1] * d[1];
            p[mt * 2 + 1] += d[2] + d[3];  q[mt * 2 + 1] += d[2] * d[2] + d[3] * d[3];
        }
    #pragma unroll
    for (int i = 0; i < 4; ++i) {
        p[i] += __shfl_xor_sync(0xffffffffu, p[i], 1);
        p[i] += __shfl_xor_sync(0xffffffffu, p[i], 2);
        q[i] += __shfl_xor_sync(0xffffffffu, q[i], 1);
        q[i] += __shfl_xor_sync(0xffffffffu, q[i], 2);
    }
    int half_ = nbase >> 6;
    if (t == 0) {
        #pragma unroll
        for (int i = 0; i < 4; ++i) {
            int r = mbase + (i >> 1) * 16 + (i & 1) * 8 + g;
            sRS[r * 2 + half_] = p[i];
            sRQ[r * 2 + half_] = q[i];
        }
    }
    __syncthreads();

    #pragma unroll
    for (int mt = 0; mt < 2; ++mt)
        #pragma unroll
        for (int jj = 0; jj < 2; ++jj) {
            int r = mbase + mt * 16 + jj * 8 + g;
            float mu = (sRS[r * 2] + sRS[r * 2 + 1]) * (1.f / 128.f);
            float qq = sRQ[r * 2] + sRQ[r * 2 + 1];
            float var = (qq - 128.f * mu * mu) * (1.f / 127.f);
            float inv = 1.f / (sqrtf(fmaxf(var, 0.f)) + 1e-6f);
            #pragma unroll
            for (int nt = 0; nt < 8; ++nt) {
                int c0 = nbase + nt * 8 + t * 2;
                float* d = acc[mt][nt];
                float v0 = sG[c0]     * (d[jj * 2]     - mu) * inv + sB2[c0];
                float v1 = sG[c0 + 1] * (d[jj * 2 + 1] - mu) * inv + sB2[c0 + 1];
                size_t off = ((size_t)blk * 128 + r) * 128 + c0;
                if (MODE == 0) {
                    *(float2*)(g_h + off) = make_float2(v0, v1);
                    *(uint32_t*)(g_hr + off) = f2h2(v0, v1);
                } else {
                    *(uint32_t*)(g_her + off) = f2h2(v0, v1);
                }
            }
        }
}

// ---------------- node projections ----------------
// y==0: P1 = h@W1q0 + b1 ; y==1: P23 = h@W1q1 + hS@W1q2
#define SM_PROJ (3 * 32768 + 512)
__global__ void __launch_bounds__(256, 2)
node_proj_k(const float* __restrict__ Lb1, int layer) {
    extern __shared__ __half smh[];
    __half* sAh = smh; __half* sW0h = smh + 16384; __half* sW1h = smh + 32768;
    float* sBias = (float*)(smh + 49152);
    uint32_t sAu = s2u(sAh), sW0u = s2u(sW0h), sW1u = s2u(sW1h);
    int tid = threadIdx.x, lane = tid & 31, wid = tid >> 5;
    int blk = blockIdx.x, which = blockIdx.y;
    int wbase = 2 + layer * 6;

    cpa_h<128>(sAu, g_hr + (size_t)blk * 16384, tid);
    cpa_h<128>(sW0u, g_Wt + (size_t)(wbase + (which ? 1 : 0)) * 16384, tid);
    if (which) cpa_h<128>(sW1u, g_Wt + (size_t)(wbase + 2) * 16384, tid);
    CP_COMMIT();
    if (tid < 128) sBias[tid] = which ? 0.f : Lb1[layer * 128 + tid];
    CP_WAIT0(); __syncthreads();

    float acc[2][8][4];
    zacc(acc);
    int mbase = (wid & 3) * 32, nbase = (wid >> 2) * 64;
    cta_gemm_h<8, 128>(sAu, sW0u, lane, mbase, nbase, acc);

    if (which) {
        __syncthreads();
        cpa_h<128>(sAu, g_hSr + (size_t)blk * 16384, tid);
        CP_COMMIT(); CP_WAIT0(); __syncthreads();
        cta_gemm_h<8, 128>(sAu, sW1u, lane, mbase, nbase, acc);
    }

    float* out = which ? g_P23 : g_P1;
    int g = lane >> 2, t = lane & 3;
    #pragma unroll
    for (int mt = 0; mt < 2; ++mt) {
        int r0 = mbase + mt * 16 + g;
        #pragma unroll
        for (int nt = 0; nt < 8; ++nt) {
            int c0 = nbase + nt * 8 + t * 2;
            float* d = acc[mt][nt];
            *(float2*)(out + ((size_t)blk * 128 + r0) * 128 + c0) =
                make_float2(d[0] + sBias[c0], d[1] + sBias[c0 + 1]);
            *(float2*)(out + ((size_t)blk * 128 + r0 + 8) * 128 + c0) =
                make_float2(d[2] + sBias[c0], d[3] + sBias[c0 + 1]);
        }
    }
}

// ---------------- fused edge layer ----------------
// halfs: sAh 0(16384) sB0h 16384 sB1h 32768 ; floats after 49152 halfs:
// sP1 512 sHold 512 sDh 512 sVm 128 sBb2 128 sBb3 128 sGidx 128 = 2048 f
// colsum scratch: float alias of sAh+sB0h (64 KB)
#define SM_EDGE (49152 * 2 + 2048 * 4)
__global__ void __launch_bounds__(256, 2)
edge_layer_k(const int* __restrict__ Eidx, const float* __restrict__ mask,
             const float* __restrict__ Lb2, const float* __restrict__ Lb3,
             const float* __restrict__ Lng, const float* __restrict__ Lnb,
             int layer, int last, float* __restrict__ outp) {
    extern __shared__ __half smh[];
    __half* sAh = smh; __half* sB0h = smh + 16384; __half* sB1h = smh + 32768;
    float* fx = (float*)(smh + 49152);
    float* sP1 = fx; float* sHold = fx + 512; float* sDh = fx + 1024;
    float* sVm = fx + 1536; float* sBb2 = fx + 1664; float* sBb3 = fx + 1792;
    int* sGidx = (int*)(fx + 1920);
    float* sCol = (float*)sAh;              // 16384 floats alias (epi3/colsum)
    uint32_t sAu = s2u(sAh), sB0u = s2u(sB0h), sB1u = s2u(sB1h);

    int tid = threadIdx.x, lane = tid & 31, wid = tid >> 5, blk = blockIdx.x;
    int base4 = blk * 4;
    int wbase = 2 + layer * 6;

    cpa_h<128>(sAu, g_her + (size_t)blk * 16384, tid);
    cpa_h<128>(sB0u, g_Wt + (size_t)(wbase + 3) * 16384, tid);   // W1q3 (he)
    cpa_h<128>(sB1u, g_Wt + (size_t)(wbase + 4) * 16384, tid);   // Lw2
    CP_COMMIT();

    if (tid < 128) {
        int nd = base4 + (tid >> 5);
        int idx = Eidx[nd * 32 + (tid & 31)];
        int gi = ((nd >> 11) << 11) + idx;
        sGidx[tid] = gi;
        sVm[tid] = mask[gi];
        sBb2[tid] = Lb2[layer * 128 + tid];
        sBb3[tid] = Lb3[layer * 128 + tid];
    }
    for (int i = tid; i < 512; i += 256) {
        sP1[i]   = g_P1[(size_t)base4 * 128 + i];
        sHold[i] = g_h [(size_t)base4 * 128 + i];
    }
    CP_WAIT0(); __syncthreads();

    int mbase = (wid & 3) * 32, nbase = (wid >> 2) * 64;
    int g = lane >> 2, t = lane & 3;
    float acc[2][8][4];

    // GEMM1: he @ W1q3
    zacc(acc);
    cta_gemm_h<8, 128>(sAu, sB0u, lane, mbase, nbase, acc);
    __syncthreads();
    cpa_h<128>(sB0u, g_Wt + (size_t)(wbase + 5) * 16384, tid);   // Lw3 prefetch
    CP_COMMIT();

    // epilogue1: relu(D + P1[node] + P23[gather]) -> sAh fp16
    #pragma unroll
    for (int mt = 0; mt < 2; ++mt) {
        int r0 = mbase + mt * 16 + g, r1 = r0 + 8;
        const float* p23a = g_P23 + (size_t)sGidx[r0] * 128;
        const float* p23b = g_P23 + (size_t)sGidx[r1] * 128;
        const float* p1a = sP1 + ((r0 >> 5) << 7);
        const float* p1b = sP1 + ((r1 >> 5) << 7);
        #pragma unroll
        for (int nt = 0; nt < 8; ++nt) {
            int c0 = nbase + nt * 8 + t * 2;
            float* d = acc[mt][nt];
            float2 qa = *(const float2*)(p23a + c0);
            float2 qb = *(const float2*)(p23b + c0);
            *(uint32_t*)((char*)sAh + swzh<128>(r0, c0) * 2) =
                f2h2(fmaxf(d[0] + qa.x + p1a[c0], 0.f), fmaxf(d[1] + qa.y + p1a[c0 + 1], 0.f));
            *(uint32_t*)((char*)sAh + swzh<128>(r1, c0) * 2) =
                f2h2(fmaxf(d[2] + qb.x + p1b[c0], 0.f), fmaxf(d[3] + qb.y + p1b[c0 + 1], 0.f));
        }
    }
    CP_WAIT0(); __syncthreads();

    // GEMM2: m1 @ Lw2
    zacc(acc);
    cta_gemm_h<8, 128>(sAu, sB1u, lane, mbase, nbase, acc);
    __syncthreads();

    // epilogue2: relu(D + b2) -> sAh fp16
    #pragma unroll
    for (int mt = 0; mt < 2; ++mt) {
        int r0 = mbase + mt * 16 + g, r1 = r0 + 8;
        #pragma unroll
        for (int nt = 0; nt < 8; ++nt) {
            int c0 = nbase + nt * 8 + t * 2;
            float* d = acc[mt][nt];
            *(uint32_t*)((char*)sAh + swzh<128>(r0, c0) * 2) =
                f2h2(fmaxf(d[0] + sBb2[c0], 0.f), fmaxf(d[1] + sBb2[c0 + 1], 0.f));
            *(uint32_t*)((char*)sAh + swzh<128>(r1, c0) * 2) =
                f2h2(fmaxf(d[2] + sBb2[c0], 0.f), fmaxf(d[3] + sBb2[c0 + 1], 0.f));
        }
    }
    __syncthreads();

    // GEMM3: m2 @ Lw3
    zacc(acc);
    cta_gemm_h<8, 128>(sAu, sB0u, lane, mbase, nbase, acc);
    __syncthreads();

    // epilogue3: (D + b3) * vmask -> sCol rotated row-major (f32)
    #pragma unroll
    for (int mt = 0; mt < 2; ++mt) {
        int r0 = mbase + mt * 16 + g, r1 = r0 + 8;
        float v0 = sVm[r0], v1 = sVm[r1];
        #pragma unroll
        for (int nt = 0; nt < 8; ++nt) {
            int c0 = nbase + nt * 8 + t * 2;
            float* d = acc[mt][nt];
            sCol[r0 * 128 + ((c0 + r0) & 127)]     = (d[0] + sBb3[c0]) * v0;
            sCol[r0 * 128 + ((c0 + 1 + r0) & 127)] = (d[1] + sBb3[c0 + 1]) * v0;
            sCol[r1 * 128 + ((c0 + r1) & 127)]     = (d[2] + sBb3[c0]) * v1;
            sCol[r1 * 128 + ((c0 + 1 + r1) & 127)] = (d[3] + sBb3[c0 + 1]) * v1;
        }
    }
    __syncthreads();

    // segment sum over K=32 edges per node
    for (int p = tid; p < 512; p += 256) {
        int gq = p >> 7, j = p & 127, rb = gq * 32;
        float s = 0.f;
        #pragma unroll
        for (int rr = 0; rr < 32; ++rr)
            s += sCol[(rb + rr) * 128 + ((j + rb + rr) & 127)];
        sDh[p] = s * (1.f / 30.f);
    }
    __syncthreads();

    // residual + LN(ddof=1) + mask
    if (tid < 128) {
        int w = tid >> 5, l = tid & 31;
        int nd = base4 + w;
        float x[4], sum = 0.f;
        #pragma unroll
        for (int c = 0; c < 4; ++c) {
            int j = l + 32 * c;
            x[c] = sHold[w * 128 + j] + sDh[w * 128 + j];
            sum += x[c];
        }
        #pragma unroll
        for (int o = 16; o; o >>= 1) sum += __shfl_xor_sync(0xffffffffu, sum, o);
        float mu = sum * (1.f / 128.f);
        float ss = 0.f;
        #pragma unroll
        for (int c = 0; c < 4; ++c) { float dd = x[c] - mu; ss += dd * dd; }
        #pragma unroll
        for (int o = 16; o; o >>= 1) ss += __shfl_xor_sync(0xffffffffu, ss, o);
        float inv = 1.f / (sqrtf(ss * (1.f / 127.f)) + 1e-6f);
        float mk = mask[nd];
        #pragma unroll
        for (int c = 0; c < 4; ++c) {
            int j = l + 32 * c;
            float v = (Lng[layer * 128 + j] * (x[c] - mu) * inv + Lnb[layer * 128 + j]) * mk;
            if (last) {
                outp[(size_t)nd * 128 + j] = v;
            } else {
                g_h [(size_t)nd * 128 + j] = v;
                g_hr[(size_t)nd * 128 + j] = __float2half_rn(v);
            }
        }
    }
}

// ---------------- launch ----------------
extern "C" void kernel_launch(void* const* d_in, const int* in_sizes, int n_in,
                              void* d_out, int out_size) {
    const float* V     = (const float*)d_in[0];
    const float* E     = (const float*)d_in[1];
    const float* hS    = (const float*)d_in[2];
    const int*   E_idx = (const int*)  d_in[3];
    const float* mask  = (const float*)d_in[4];
    const float* Wv_w  = (const float*)d_in[5];
    const float* Wv_b  = (const float*)d_in[6];
    const float* Wv_g  = (const float*)d_in[7];
    const float* Wv_b2 = (const float*)d_in[8];
    const float* We_w  = (const float*)d_in[9];
    const float* We_b  = (const float*)d_in[10];
    const float* We_g  = (const float*)d_in[11];
    const float* We_b2 = (const float*)d_in[12];
    const float* Lw1   = (const float*)d_in[13];
    const float* Lb1   = (const float*)d_in[14];
    const float* Lw2   = (const float*)d_in[15];
    const float* Lb2   = (const float*)d_in[16];
    const float* Lw3   = (const float*)d_in[17];
    const float* Lb3   = (const float*)d_in[18];
    const float* Ln_g  = (const float*)d_in[19];
    const float* Ln_b  = (const float*)d_in[20];
    float* out = (float*)d_out;

    cudaFuncSetAttribute(embed_k<64, 0>, cudaFuncAttributeMaxDynamicSharedMemorySize, SM_EMB);
    cudaFuncSetAttribute(embed_k<48, 1>, cudaFuncAttributeMaxDynamicSharedMemorySize, SM_EMB);
    cudaFuncSetAttribute(node_proj_k,    cudaFuncAttributeMaxDynamicSharedMemorySize, SM_PROJ);
    cudaFuncSetAttribute(edge_layer_k,   cudaFuncAttributeMaxDynamicSharedMemorySize, SM_EDGE);

    pack_w<<<20, 256>>>(Wv_w, We_w, Lw1, Lw2, Lw3);
    pack_hs<<<128, 256>>>(hS);
    embed_k<64, 0><<<32,   256, SM_EMB>>>(V, Wv_b, Wv_g, Wv_b2, 0);
    embed_k<48, 1><<<1024, 256, SM_EMB>>>(E, We_b, We_g, We_b2, 1);

    for (int layer = 0; layer < 3; ++layer) {
        node_proj_k<<<dim3(32, 2), 256, SM_PROJ>>>(Lb1, layer);
        edge_layer_k<<<1024, 256, SM_EDGE>>>(E_idx, mask, Lb2, Lb3, Ln_g, Ln_b,
                                             layer, layer == 2 ? 1 : 0, out);
    }
}

// round 7
// speedup vs baseline: 7.5969x; 1.1455x over previous
#include <cuda_runtime.h>
#include <cuda_fp16.h>
#include <cstdint>
#include <math.h>

#define NODES 4096
#define EDGES 131072

// ---------------- device scratch (static globals) ----------------
__device__ __align__(256) __half g_her[EDGES * 128];  // fp16 edge embeddings
__device__ __align__(256) float  g_h  [NODES * 128];  // exact node state
__device__ __align__(256) __half g_hr [NODES * 128];  // fp16 node state
__device__ __align__(256) __half g_hSr[NODES * 128];  // fp16 hS
__device__ __align__(256) float  g_P1 [NODES * 128];
__device__ __align__(256) float  g_P23[NODES * 128];
__device__ __align__(256) __half g_S2h[NODES * 128];  // aggregated m2 (fp16)
__device__ __align__(256) float  g_vs [NODES];        // sum of vmask per node
__device__ __align__(256) __half g_Wt [20 * 16384];   // weights Bt[n][k] fp16

// ---------------- helpers ----------------
__device__ __forceinline__ uint32_t s2u(const void* p) {
    uint32_t a;
    asm("{ .reg .u64 t; cvta.to.shared.u64 t, %1; cvt.u32.u64 %0, t; }" : "=r"(a) : "l"(p));
    return a;
}
__device__ __forceinline__ uint32_t f2h2(float x, float y) {
    __half2 h = __floats2half2_rn(x, y);
    return *(uint32_t*)&h;
}
__device__ __forceinline__ void ldsm4(uint32_t d[4], uint32_t a) {
    asm volatile("ldmatrix.sync.aligned.m8n8.x4.shared.b16 {%0,%1,%2,%3}, [%4];"
                 : "=r"(d[0]), "=r"(d[1]), "=r"(d[2]), "=r"(d[3]) : "r"(a));
}
__device__ __forceinline__ void mma16(float d[4], const uint32_t a[4], uint32_t b0, uint32_t b1) {
    asm volatile("mma.sync.aligned.m16n8k16.row.col.f32.f16.f16.f32 "
                 "{%0,%1,%2,%3}, {%4,%5,%6,%7}, {%8,%9}, {%0,%1,%2,%3};"
                 : "+f"(d[0]), "+f"(d[1]), "+f"(d[2]), "+f"(d[3])
                 : "r"(a[0]), "r"(a[1]), "r"(a[2]), "r"(a[3]), "r"(b0), "r"(b1));
}
#define CP16(dst, src) asm volatile("cp.async.cg.shared.global [%0], [%1], 16;" :: "r"(dst), "l"(src))
#define CP_COMMIT()    asm volatile("cp.async.commit_group;")
#define CP_WAIT0()     asm volatile("cp.async.wait_group 0;" ::: "memory")

// swizzled HALF index in a 128 x ROWH half tile (XOR granule = 8 halfs = 16B)
template <int ROWH>
__device__ __forceinline__ int swzh(int r, int c) { return r * ROWH + (c ^ ((r & 7) << 3)); }

template <int ROWH>
__device__ __forceinline__ void cpa_h(uint32_t sDst, const __half* __restrict__ g, int tid) {
    const int NCH = 128 * ROWH / 8;
    #pragma unroll 4
    for (int i = tid; i < NCH; i += 256) {
        int r = i / (ROWH / 8), c = (i % (ROWH / 8)) * 8;
        CP16(sDst + swzh<ROWH>(r, c) * 2, g + (size_t)r * ROWH + c);
    }
}

__device__ __forceinline__ void zacc(float acc[2][8][4]) {
    #pragma unroll
    for (int i = 0; i < 2; ++i)
        #pragma unroll
        for (int j = 0; j < 8; ++j)
            #pragma unroll
            for (int k = 0; k < 4; ++k) acc[i][j][k] = 0.f;
}

// CTA GEMM fp16: D[128,128] += A[128,K] @ Bt[128,K]^T, 8 warps, warp tile 32x64
template <int KH, int ROWH>   // KH = K/16
__device__ __forceinline__ void cta_gemm_h(uint32_t sAu, uint32_t sBu, int lane,
                                           int mbase, int nbase, float acc[2][8][4]) {
    int arow = lane & 15, acol = (lane >> 4) << 3;
    int bn = ((lane >> 4) & 1) * 8 + (lane & 7), bk = ((lane >> 3) & 1) * 8;
    #pragma unroll
    for (int k0 = 0; k0 < KH; ++k0) {
        int kh = k0 * 16;
        uint32_t a0[4], a1[4];
        ldsm4(a0, sAu + swzh<ROWH>(mbase + arow,      kh + acol) * 2);
        ldsm4(a1, sAu + swzh<ROWH>(mbase + 16 + arow, kh + acol) * 2);
        #pragma unroll
        for (int q8 = 0; q8 < 4; ++q8) {
            uint32_t b[4];
            ldsm4(b, sBu + swzh<ROWH>(nbase + q8 * 16 + bn, kh + bk) * 2);
            mma16(acc[0][q8 * 2],     a0, b[0], b[1]);
            mma16(acc[0][q8 * 2 + 1], a0, b[2], b[3]);
            mma16(acc[1][q8 * 2],     a1, b[0], b[1]);
            mma16(acc[1][q8 * 2 + 1], a1, b[2], b[3]);
        }
    }
}

// ---------------- pack: weights -> Bt[n][k] fp16 ----------------
__global__ void pack_w(const float* __restrict__ Wv, const float* __restrict__ We,
                       const float* __restrict__ Lw1, const float* __restrict__ Lw2,
                       const float* __restrict__ Lw3) {
    int m = blockIdx.x;
    const float* src; int Kin, ROWH;
    if (m == 0)      { src = Wv; Kin = 64; ROWH = 64; }
    else if (m == 1) { src = We; Kin = 48; ROWH = 64; }
    else {
        int l = (m - 2) / 6, q = (m - 2) % 6;
        if (q < 4)       src = Lw1 + ((size_t)l * 512 + q * 128) * 128;
        else if (q == 4) src = Lw2 + (size_t)l * 16384;
        else             src = Lw3 + (size_t)l * 16384;
        Kin = 128; ROWH = 128;
    }
    __half* dst = g_Wt + (size_t)m * 16384;
    int tot = 128 * ROWH;
    for (int i = threadIdx.x; i < tot; i += blockDim.x) {
        int n = i / ROWH, k = i % ROWH;
        dst[i] = (k < Kin) ? __float2half_rn(src[(size_t)k * 128 + n]) : __half(0.f);
    }
}
__global__ void pack_hs(const float* __restrict__ hS) {
    for (int i = blockIdx.x * blockDim.x + threadIdx.x; i < NODES * 128;
         i += gridDim.x * blockDim.x)
        g_hSr[i] = __float2half_rn(hS[i]);
}
__global__ void compute_vs(const int* __restrict__ Eidx, const float* __restrict__ mask) {
    int nd = blockIdx.x * blockDim.x + threadIdx.x;
    if (nd >= NODES) return;
    int b = nd >> 11;
    float s = 0.f;
    #pragma unroll 8
    for (int k = 0; k < 32; ++k) s += mask[(b << 11) + Eidx[nd * 32 + k]];
    g_vs[nd] = s;
}

// ---------------- embed: norm(X@W + b), LN from accumulators ----------------
#define SM_EMB (2 * 16384 + 896 * 4)
template <int KIN, int MODE>  // MODE 0: node (g_h + g_hr), 1: edge (g_her)
__global__ void __launch_bounds__(256, 2)
embed_k(const float* __restrict__ X, const float* __restrict__ bb,
        const float* __restrict__ gg, const float* __restrict__ b2, int wslot) {
    extern __shared__ __half smh[];
    __half* sAh = smh; __half* sWh = smh + 8192;
    float* fx = (float*)(smh + 16384);
    float* sBias = fx; float* sG = fx + 128; float* sB2 = fx + 256;
    float* sRS = fx + 384; float* sRQ = fx + 640;
    uint32_t sAu = s2u(sAh), sWu = s2u(sWh);
    int tid = threadIdx.x, lane = tid & 31, wid = tid >> 5, blk = blockIdx.x;

    cpa_h<64>(sWu, g_Wt + (size_t)wslot * 16384, tid);
    CP_COMMIT();
    for (int i = tid; i < 1024; i += 256) {
        int r = i >> 3, gc = (i & 7) * 8;
        uint4 u;
        if (gc < KIN) {
            const float* xp = X + ((size_t)blk * 128 + r) * KIN + gc;
            float4 v0 = *(const float4*)(xp);
            float4 v1 = *(const float4*)(xp + 4);
            u.x = f2h2(v0.x, v0.y); u.y = f2h2(v0.z, v0.w);
            u.z = f2h2(v1.x, v1.y); u.w = f2h2(v1.z, v1.w);
        } else u = make_uint4(0, 0, 0, 0);
        *(uint4*)((char*)sAh + swzh<64>(r, gc) * 2) = u;
    }
    if (tid < 128) { sBias[tid] = bb[tid]; sG[tid] = gg[tid]; sB2[tid] = b2[tid]; }
    CP_WAIT0(); __syncthreads();

    float acc[2][8][4];
    zacc(acc);
    int mbase = (wid & 3) * 32, nbase = (wid >> 2) * 64;
    cta_gemm_h<4, 64>(sAu, sWu, lane, mbase, nbase, acc);

    int g = lane >> 2, t = lane & 3;
    float p[4] = {0, 0, 0, 0}, q[4] = {0, 0, 0, 0};
    #pragma unroll
    for (int mt = 0; mt < 2; ++mt)
        #pragma unroll
        for (int nt = 0; nt < 8; ++nt) {
            int c0 = nbase + nt * 8 + t * 2;
            float* d = acc[mt][nt];
            d[0] += sBias[c0]; d[1] += sBias[c0 + 1];
            d[2] += sBias[c0]; d[3] += sBias[c0 + 1];
            p[mt * 2]     += d[0] + d[1];  q[mt * 2]     += d[0] * d[0] + d[1] * d[1];
            p[mt * 2 + 1] += d[2] + d[3];  q[mt * 2 + 1] += d[2] * d[2] + d[3] * d[3];
        }
    #pragma unroll
    for (int i = 0; i < 4; ++i) {
        p[i] += __shfl_xor_sync(0xffffffffu, p[i], 1);
        p[i] += __shfl_xor_sync(0xffffffffu, p[i], 2);
        q[i] += __shfl_xor_sync(0xffffffffu, q[i], 1);
        q[i] += __shfl_xor_sync(0xffffffffu, q[i], 2);
    }
    int half_ = nbase >> 6;
    if (t == 0) {
        #pragma unroll
        for (int i = 0; i < 4; ++i) {
            int r = mbase + (i >> 1) * 16 + (i & 1) * 8 + g;
            sRS[r * 2 + half_] = p[i];
            sRQ[r * 2 + half_] = q[i];
        }
    }
    __syncthreads();

    #pragma unroll
    for (int mt = 0; mt < 2; ++mt)
        #pragma unroll
        for (int jj = 0; jj < 2; ++jj) {
            int r = mbase + mt * 16 + jj * 8 + g;
            float mu = (sRS[r * 2] + sRS[r * 2 + 1]) * (1.f / 128.f);
            float qq = sRQ[r * 2] + sRQ[r * 2 + 1];
            float var = (qq - 128.f * mu * mu) * (1.f / 127.f);
            float inv = 1.f / (sqrtf(fmaxf(var, 0.f)) + 1e-6f);
            #pragma unroll
            for (int nt = 0; nt < 8; ++nt) {
                int c0 = nbase + nt * 8 + t * 2;
                float* d = acc[mt][nt];
                float v0 = sG[c0]     * (d[jj * 2]     - mu) * inv + sB2[c0];
                float v1 = sG[c0 + 1] * (d[jj * 2 + 1] - mu) * inv + sB2[c0 + 1];
                size_t off = ((size_t)blk * 128 + r) * 128 + c0;
                if (MODE == 0) {
                    *(float2*)(g_h + off) = make_float2(v0, v1);
                    *(uint32_t*)(g_hr + off) = f2h2(v0, v1);
                } else {
                    *(uint32_t*)(g_her + off) = f2h2(v0, v1);
                }
            }
        }
}

// ---------------- node projections ----------------
#define SM_PROJ (3 * 32768 + 512)
__global__ void __launch_bounds__(256, 2)
node_proj_k(const float* __restrict__ Lb1, int layer) {
    extern __shared__ __half smh[];
    __half* sAh = smh; __half* sW0h = smh + 16384; __half* sW1h = smh + 32768;
    float* sBias = (float*)(smh + 49152);
    uint32_t sAu = s2u(sAh), sW0u = s2u(sW0h), sW1u = s2u(sW1h);
    int tid = threadIdx.x, lane = tid & 31, wid = tid >> 5;
    int blk = blockIdx.x, which = blockIdx.y;
    int wbase = 2 + layer * 6;

    cpa_h<128>(sAu, g_hr + (size_t)blk * 16384, tid);
    cpa_h<128>(sW0u, g_Wt + (size_t)(wbase + (which ? 1 : 0)) * 16384, tid);
    if (which) cpa_h<128>(sW1u, g_Wt + (size_t)(wbase + 2) * 16384, tid);
    CP_COMMIT();
    if (tid < 128) sBias[tid] = which ? 0.f : Lb1[layer * 128 + tid];
    CP_WAIT0(); __syncthreads();

    float acc[2][8][4];
    zacc(acc);
    int mbase = (wid & 3) * 32, nbase = (wid >> 2) * 64;
    cta_gemm_h<8, 128>(sAu, sW0u, lane, mbase, nbase, acc);

    if (which) {
        __syncthreads();
        cpa_h<128>(sAu, g_hSr + (size_t)blk * 16384, tid);
        CP_COMMIT(); CP_WAIT0(); __syncthreads();
        cta_gemm_h<8, 128>(sAu, sW1u, lane, mbase, nbase, acc);
    }

    float* out = which ? g_P23 : g_P1;
    int g = lane >> 2, t = lane & 3;
    #pragma unroll
    for (int mt = 0; mt < 2; ++mt) {
        int r0 = mbase + mt * 16 + g;
        #pragma unroll
        for (int nt = 0; nt < 8; ++nt) {
            int c0 = nbase + nt * 8 + t * 2;
            float* d = acc[mt][nt];
            *(float2*)(out + ((size_t)blk * 128 + r0) * 128 + c0) =
                make_float2(d[0] + sBias[c0], d[1] + sBias[c0 + 1]);
            *(float2*)(out + ((size_t)blk * 128 + r0 + 8) * 128 + c0) =
                make_float2(d[2] + sBias[c0], d[3] + sBias[c0 + 1]);
        }
    }
}

// ---------------- edge layer: 2 GEMMs + in-register weighted aggregation ----
// halfs: sAh 0(16384) sB0h 16384 sB1h 32768 ; floats: sP1 512 sVm 128 sBb2 128
// sGidx 128
#define SM_EDGE (49152 * 2 + 896 * 4)
__global__ void __launch_bounds__(256, 2)
edge_layer_k(const int* __restrict__ Eidx, const float* __restrict__ mask,
             const float* __restrict__ Lb2, int layer) {
    extern __shared__ __half smh[];
    __half* sAh = smh; __half* sB0h = smh + 16384; __half* sB1h = smh + 32768;
    float* fx = (float*)(smh + 49152);
    float* sP1 = fx; float* sVm = fx + 512; float* sBb2 = fx + 640;
    int* sGidx = (int*)(fx + 768);
    uint32_t sAu = s2u(sAh), sB0u = s2u(sB0h), sB1u = s2u(sB1h);

    int tid = threadIdx.x, lane = tid & 31, wid = tid >> 5, blk = blockIdx.x;
    int base4 = blk * 4;
    int wbase = 2 + layer * 6;

    cpa_h<128>(sAu, g_her + (size_t)blk * 16384, tid);
    cpa_h<128>(sB0u, g_Wt + (size_t)(wbase + 3) * 16384, tid);   // W1q3 (he)
    cpa_h<128>(sB1u, g_Wt + (size_t)(wbase + 4) * 16384, tid);   // Lw2
    CP_COMMIT();

    if (tid < 128) {
        int nd = base4 + (tid >> 5);
        int idx = Eidx[nd * 32 + (tid & 31)];
        int gi = ((nd >> 11) << 11) + idx;
        sGidx[tid] = gi;
        sVm[tid] = mask[gi];
        sBb2[tid] = Lb2[layer * 128 + tid];
    }
    for (int i = tid; i < 512; i += 256)
        sP1[i] = g_P1[(size_t)base4 * 128 + i];
    CP_WAIT0(); __syncthreads();

    int mbase = (wid & 3) * 32, nbase = (wid >> 2) * 64;
    int g = lane >> 2, t = lane & 3;
    float acc[2][8][4];

    // GEMM1: he @ W1q3
    zacc(acc);
    cta_gemm_h<8, 128>(sAu, sB0u, lane, mbase, nbase, acc);
    __syncthreads();

    // epilogue1: relu(D + P1[node] + P23[gather]) -> sAh fp16
    #pragma unroll
    for (int mt = 0; mt < 2; ++mt) {
        int r0 = mbase + mt * 16 + g, r1 = r0 + 8;
        const float* p23a = g_P23 + (size_t)sGidx[r0] * 128;
        const float* p23b = g_P23 + (size_t)sGidx[r1] * 128;
        const float* p1a = sP1 + ((r0 >> 5) << 7);
        const float* p1b = sP1 + ((r1 >> 5) << 7);
        #pragma unroll
        for (int nt = 0; nt < 8; ++nt) {
            int c0 = nbase + nt * 8 + t * 2;
            float* d = acc[mt][nt];
            float2 qa = *(const float2*)(p23a + c0);
            float2 qb = *(const float2*)(p23b + c0);
            *(uint32_t*)((char*)sAh + swzh<128>(r0, c0) * 2) =
                f2h2(fmaxf(d[0] + qa.x + p1a[c0], 0.f), fmaxf(d[1] + qa.y + p1a[c0 + 1], 0.f));
            *(uint32_t*)((char*)sAh + swzh<128>(r1, c0) * 2) =
                f2h2(fmaxf(d[2] + qb.x + p1b[c0], 0.f), fmaxf(d[3] + qb.y + p1b[c0 + 1], 0.f));
        }
    }
    __syncthreads();

    // GEMM2: m1 @ Lw2
    zacc(acc);
    cta_gemm_h<8, 128>(sAu, sB1u, lane, mbase, nbase, acc);

    // epilogue2: weighted segment sum of relu(D + b2) over the warp's node
    float part[8][2];
    #pragma unroll
    for (int nt = 0; nt < 8; ++nt) { part[nt][0] = 0.f; part[nt][1] = 0.f; }
    #pragma unroll
    for (int mt = 0; mt < 2; ++mt) {
        int r0 = mbase + mt * 16 + g, r1 = r0 + 8;
        float v0 = sVm[r0], v1 = sVm[r1];
        #pragma unroll
        for (int nt = 0; nt < 8; ++nt) {
            int c0 = nbase + nt * 8 + t * 2;
            float* d = acc[mt][nt];
            part[nt][0] += fmaxf(d[0] + sBb2[c0],     0.f) * v0
                         + fmaxf(d[2] + sBb2[c0],     0.f) * v1;
            part[nt][1] += fmaxf(d[1] + sBb2[c0 + 1], 0.f) * v0
                         + fmaxf(d[3] + sBb2[c0 + 1], 0.f) * v1;
        }
    }
    #pragma unroll
    for (int nt = 0; nt < 8; ++nt)
        #pragma unroll
        for (int j = 0; j < 2; ++j) {
            float v = part[nt][j];
            v += __shfl_xor_sync(0xffffffffu, v, 4);
            v += __shfl_xor_sync(0xffffffffu, v, 8);
            v += __shfl_xor_sync(0xffffffffu, v, 16);
            part[nt][j] = v;
        }
    if (g == 0) {
        int node = base4 + (wid & 3);
        #pragma unroll
        for (int nt = 0; nt < 8; ++nt) {
            int c0 = nbase + nt * 8 + t * 2;
            *(uint32_t*)(g_S2h + (size_t)node * 128 + c0) = f2h2(part[nt][0], part[nt][1]);
        }
    }
}

// ---------------- node fin: dh = S2@W3/30 + vs*b3/30 ; h = LN(h+dh)*mask ----
// halfs: sAh 0(16384) sWh 16384 ; floats: sB3 128 sLg 128 sLb 128 sVs 128
// sMk 128 sRS 256 sRQ 256 = 1152
#define SM_FIN (2 * 32768 + 1152 * 4)
__global__ void __launch_bounds__(256)
node_fin_k(const float* __restrict__ mask, const float* __restrict__ Lb3,
           const float* __restrict__ Lng, const float* __restrict__ Lnb,
           int layer, int last, float* __restrict__ outp) {
    extern __shared__ __half smh[];
    __half* sAh = smh; __half* sWh = smh + 16384;
    float* fx = (float*)(smh + 32768);
    float* sB3 = fx; float* sLg = fx + 128; float* sLb = fx + 256;
    float* sVs = fx + 384; float* sMk = fx + 512;
    float* sRS = fx + 640; float* sRQ = fx + 896;
    uint32_t sAu = s2u(sAh), sWu = s2u(sWh);
    int tid = threadIdx.x, lane = tid & 31, wid = tid >> 5, blk = blockIdx.x;
    int wbase = 2 + layer * 6;

    cpa_h<128>(sAu, g_S2h + (size_t)blk * 16384, tid);
    cpa_h<128>(sWu, g_Wt + (size_t)(wbase + 5) * 16384, tid);   // Lw3
    CP_COMMIT();
    if (tid < 128) {
        sB3[tid] = Lb3[layer * 128 + tid];
        sLg[tid] = Lng[layer * 128 + tid];
        sLb[tid] = Lnb[layer * 128 + tid];
        sVs[tid] = g_vs[blk * 128 + tid];
        sMk[tid] = mask[blk * 128 + tid];
    }
    CP_WAIT0(); __syncthreads();

    float acc[2][8][4];
    zacc(acc);
    int mbase = (wid & 3) * 32, nbase = (wid >> 2) * 64;
    cta_gemm_h<8, 128>(sAu, sWu, lane, mbase, nbase, acc);

    // x = d/30 + vs*b3/30 + h_old ; row sums for LN
    const float i30 = 1.f / 30.f;
    int g = lane >> 2, t = lane & 3;
    float p[4] = {0, 0, 0, 0}, q[4] = {0, 0, 0, 0};
    #pragma unroll
    for (int mt = 0; mt < 2; ++mt) {
        int r0 = mbase + mt * 16 + g, r1 = r0 + 8;
        float vs0 = sVs[r0] * i30, vs1 = sVs[r1] * i30;
        #pragma unroll
        for (int nt = 0; nt < 8; ++nt) {
            int c0 = nbase + nt * 8 + t * 2;
            float* d = acc[mt][nt];
            float2 h0 = *(const float2*)(g_h + ((size_t)(blk * 128 + r0)) * 128 + c0);
            float2 h1 = *(const float2*)(g_h + ((size_t)(blk * 128 + r1)) * 128 + c0);
            d[0] = d[0] * i30 + vs0 * sB3[c0]     + h0.x;
            d[1] = d[1] * i30 + vs0 * sB3[c0 + 1] + h0.y;
            d[2] = d[2] * i30 + vs1 * sB3[c0]     + h1.x;
            d[3] = d[3] * i30 + vs1 * sB3[c0 + 1] + h1.y;
            p[mt * 2]     += d[0] + d[1];  q[mt * 2]     += d[0] * d[0] + d[1] * d[1];
            p[mt * 2 + 1] += d[2] + d[3];  q[mt * 2 + 1] += d[2] * d[2] + d[3] * d[3];
        }
    }
    #pragma unroll
    for (int i = 0; i < 4; ++i) {
        p[i] += __shfl_xor_sync(0xffffffffu, p[i], 1);
        p[i] += __shfl_xor_sync(0xffffffffu, p[i], 2);
        q[i] += __shfl_xor_sync(0xffffffffu, q[i], 1);
        q[i] += __shfl_xor_sync(0xffffffffu, q[i], 2);
    }
    int half_ = nbase >> 6;
    if (t == 0) {
        #pragma unroll
        for (int i = 0; i < 4; ++i) {
            int r = mbase + (i >> 1) * 16 + (i & 1) * 8 + g;
            sRS[r * 2 + half_] = p[i];
            sRQ[r * 2 + half_] = q[i];
        }
    }
    __syncthreads();

    #pragma unroll
    for (int mt = 0; mt < 2; ++mt)
        #pragma unroll
        for (int jj = 0; jj < 2; ++jj) {
            int r = mbase + mt * 16 + jj * 8 + g;
            float mu = (sRS[r * 2] + sRS[r * 2 + 1]) * (1.f / 128.f);
            float qq = sRQ[r * 2] + sRQ[r * 2 + 1];
            float var = (qq - 128.f * mu * mu) * (1.f / 127.f);
            float inv = 1.f / (sqrtf(fmaxf(var, 0.f)) + 1e-6f);
            float mk = sMk[r];
            #pragma unroll
            for (int nt = 0; nt < 8; ++nt) {
                int c0 = nbase + nt * 8 + t * 2;
                float* d = acc[mt][nt];
                float v0 = (sLg[c0]     * (d[jj * 2]     - mu) * inv + sLb[c0])     * mk;
                float v1 = (sLg[c0 + 1] * (d[jj * 2 + 1] - mu) * inv + sLb[c0 + 1]) * mk;
                size_t off = ((size_t)blk * 128 + r) * 128 + c0;
                if (last) {
                    *(float2*)(outp + off) = make_float2(v0, v1);
                } else {
                    *(float2*)(g_h + off) = make_float2(v0, v1);
                    *(uint32_t*)(g_hr + off) = f2h2(v0, v1);
                }
            }
        }
}

// ---------------- launch ----------------
extern "C" void kernel_launch(void* const* d_in, const int* in_sizes, int n_in,
                              void* d_out, int out_size) {
    const float* V     = (const float*)d_in[0];
    const float* E     = (const float*)d_in[1];
    const float* hS    = (const float*)d_in[2];
    const int*   E_idx = (const int*)  d_in[3];
    const float* mask  = (const float*)d_in[4];
    const float* Wv_w  = (const float*)d_in[5];
    const float* Wv_b  = (const float*)d_in[6];
    const float* Wv_g  = (const float*)d_in[7];
    const float* Wv_b2 = (const float*)d_in[8];
    const float* We_w  = (const float*)d_in[9];
    const float* We_b  = (const float*)d_in[10];
    const float* We_g  = (const float*)d_in[11];
    const float* We_b2 = (const float*)d_in[12];
    const float* Lw1   = (const float*)d_in[13];
    const float* Lb1   = (const float*)d_in[14];
    const float* Lw2   = (const float*)d_in[15];
    const float* Lb2   = (const float*)d_in[16];
    const float* Lw3   = (const float*)d_in[17];
    const float* Lb3   = (const float*)d_in[18];
    const float* Ln_g  = (const float*)d_in[19];
    const float* Ln_b  = (const float*)d_in[20];
    float* out = (float*)d_out;

    cudaFuncSetAttribute(embed_k<64, 0>, cudaFuncAttributeMaxDynamicSharedMemorySize, SM_EMB);
    cudaFuncSetAttribute(embed_k<48, 1>, cudaFuncAttributeMaxDynamicSharedMemorySize, SM_EMB);
    cudaFuncSetAttribute(node_proj_k,    cudaFuncAttributeMaxDynamicSharedMemorySize, SM_PROJ);
    cudaFuncSetAttribute(edge_layer_k,   cudaFuncAttributeMaxDynamicSharedMemorySize, SM_EDGE);
    cudaFuncSetAttribute(node_fin_k,     cudaFuncAttributeMaxDynamicSharedMemorySize, SM_FIN);

    pack_w<<<20, 256>>>(Wv_w, We_w, Lw1, Lw2, Lw3);
    pack_hs<<<128, 256>>>(hS);
    compute_vs<<<16, 256>>>(E_idx, mask);
    embed_k<64, 0><<<32,   256, SM_EMB>>>(V, Wv_b, Wv_g, Wv_b2, 0);
    embed_k<48, 1><<<1024, 256, SM_EMB>>>(E, We_b, We_g, We_b2, 1);

    for (int layer = 0; layer < 3; ++layer) {
        node_proj_k<<<dim3(32, 2), 256, SM_PROJ>>>(Lb1, layer);
        edge_layer_k<<<1024, 256, SM_EDGE>>>(E_idx, mask, Lb2, layer);
        node_fin_k<<<32, 256, SM_FIN>>>(mask, Lb3, Ln_g, Ln_b,
                                        layer, layer == 2 ? 1 : 0, out);
    }
}

// round 8
// speedup vs baseline: 8.0061x; 1.0539x over previous
#include <cuda_runtime.h>
#include <cuda_fp16.h>
#include <cstdint>
#include <math.h>

#define NODES 4096
#define EDGES 131072

// ---------------- device scratch ----------------
__device__ __align__(256) __half g_her[EDGES * 128];
__device__ __align__(256) float  g_h  [NODES * 128];
__device__ __align__(256) __half g_hSr[NODES * 128];
__device__ __align__(256) float  g_P1 [NODES * 128];
__device__ __align__(256) float  g_P23[NODES * 128];
__device__ __align__(256) __half g_S2h[NODES * 128];
__device__ __align__(256) float  g_vs [NODES];
__device__ __align__(256) __half g_Wt [20 * 16384];

// ---------------- helpers ----------------
__device__ __forceinline__ uint32_t s2u(const void* p) {
    uint32_t a;
    asm("{ .reg .u64 t; cvta.to.shared.u64 t, %1; cvt.u32.u64 %0, t; }" : "=r"(a) : "l"(p));
    return a;
}
__device__ __forceinline__ uint32_t f2h2(float x, float y) {
    __half2 h = __floats2half2_rn(x, y);
    return *(uint32_t*)&h;
}
__device__ __forceinline__ void ldsm4(uint32_t d[4], uint32_t a) {
    asm volatile("ldmatrix.sync.aligned.m8n8.x4.shared.b16 {%0,%1,%2,%3}, [%4];"
                 : "=r"(d[0]), "=r"(d[1]), "=r"(d[2]), "=r"(d[3]) : "r"(a));
}
__device__ __forceinline__ void mma16(float d[4], const uint32_t a[4], uint32_t b0, uint32_t b1) {
    asm volatile("mma.sync.aligned.m16n8k16.row.col.f32.f16.f16.f32 "
                 "{%0,%1,%2,%3}, {%4,%5,%6,%7}, {%8,%9}, {%0,%1,%2,%3};"
                 : "+f"(d[0]), "+f"(d[1]), "+f"(d[2]), "+f"(d[3])
                 : "r"(a[0]), "r"(a[1]), "r"(a[2]), "r"(a[3]), "r"(b0), "r"(b1));
}
#define CP16(dst, src) asm volatile("cp.async.cg.shared.global [%0], [%1], 16;" :: "r"(dst), "l"(src))
#define CP_COMMIT()    asm volatile("cp.async.commit_group;")
#define CP_WAIT0()     asm volatile("cp.async.wait_group 0;" ::: "memory")
#define CP_WAIT1()     asm volatile("cp.async.wait_group 1;" ::: "memory")

template <int ROWH>
__device__ __forceinline__ int swzh(int r, int c) { return r * ROWH + (c ^ ((r & 7) << 3)); }

template <int ROWH>
__device__ __forceinline__ void cpa_h(uint32_t sDst, const __half* __restrict__ g, int tid) {
    const int NCH = 128 * ROWH / 8;
    #pragma unroll 4
    for (int i = tid; i < NCH; i += 256) {
        int r = i / (ROWH / 8), c = (i % (ROWH / 8)) * 8;
        CP16(sDst + swzh<ROWH>(r, c) * 2, g + (size_t)r * ROWH + c);
    }
}

__device__ __forceinline__ void zacc(float acc[2][8][4]) {
    #pragma unroll
    for (int i = 0; i < 2; ++i)
        #pragma unroll
        for (int j = 0; j < 8; ++j)
            #pragma unroll
            for (int k = 0; k < 4; ++k) acc[i][j][k] = 0.f;
}

template <int KH, int ROWH>
__device__ __forceinline__ void cta_gemm_h(uint32_t sAu, uint32_t sBu, int lane,
                                           int mbase, int nbase, float acc[2][8][4]) {
    int arow = lane & 15, acol = (lane >> 4) << 3;
    int bn = ((lane >> 4) & 1) * 8 + (lane & 7), bk = ((lane >> 3) & 1) * 8;
    #pragma unroll
    for (int k0 = 0; k0 < KH; ++k0) {
        int kh = k0 * 16;
        uint32_t a0[4], a1[4];
        ldsm4(a0, sAu + swzh<ROWH>(mbase + arow,      kh + acol) * 2);
        ldsm4(a1, sAu + swzh<ROWH>(mbase + 16 + arow, kh + acol) * 2);
        #pragma unroll
        for (int q8 = 0; q8 < 4; ++q8) {
            uint32_t b[4];
            ldsm4(b, sBu + swzh<ROWH>(nbase + q8 * 16 + bn, kh + bk) * 2);
            mma16(acc[0][q8 * 2],     a0, b[0], b[1]);
            mma16(acc[0][q8 * 2 + 1], a0, b[2], b[3]);
            mma16(acc[1][q8 * 2],     a1, b[0], b[1]);
            mma16(acc[1][q8 * 2 + 1], a1, b[2], b[3]);
        }
    }
}

// ---------------- pack kernels ----------------
__global__ void pack_w(const float* __restrict__ Wv, const float* __restrict__ We,
                       const float* __restrict__ Lw1, const float* __restrict__ Lw2,
                       const float* __restrict__ Lw3) {
    int m = blockIdx.x;
    const float* src; int Kin, ROWH;
    if (m == 0)      { src = Wv; Kin = 64; ROWH = 64; }
    else if (m == 1) { src = We; Kin = 48; ROWH = 64; }
    else {
        int l = (m - 2) / 6, q = (m - 2) % 6;
        if (q < 4)       src = Lw1 + ((size_t)l * 512 + q * 128) * 128;
        else if (q == 4) src = Lw2 + (size_t)l * 16384;
        else             src = Lw3 + (size_t)l * 16384;
        Kin = 128; ROWH = 128;
    }
    __half* dst = g_Wt + (size_t)m * 16384;
    int tot = 128 * ROWH;
    for (int i = threadIdx.x; i < tot; i += blockDim.x) {
        int n = i / ROWH, k = i % ROWH;
        dst[i] = (k < Kin) ? __float2half_rn(src[(size_t)k * 128 + n]) : __half(0.f);
    }
}
__global__ void pack_hs(const float* __restrict__ hS) {
    for (int i = blockIdx.x * blockDim.x + threadIdx.x; i < NODES * 128;
         i += gridDim.x * blockDim.x)
        g_hSr[i] = __float2half_rn(hS[i]);
}
__global__ void compute_vs(const int* __restrict__ Eidx, const float* __restrict__ mask) {
    int nd = blockIdx.x * blockDim.x + threadIdx.x;
    if (nd >= NODES) return;
    int b = nd >> 11;
    float s = 0.f;
    #pragma unroll 8
    for (int k = 0; k < 32; ++k) s += mask[(b << 11) + Eidx[nd * 32 + k]];
    g_vs[nd] = s;
}

// ---------------- embed_edge: persistent, double-buffered staging ----------
// halfs: sAh 8192, sWh 8192 ; floats: stage 2*6144, bias/g/b2 384, RS/RQ 512
#define SM_EE (16384 * 2 + (12288 + 896) * 4)
__global__ void __launch_bounds__(256, 2)
embed_edge_k(const float* __restrict__ E, const float* __restrict__ bb,
             const float* __restrict__ gg, const float* __restrict__ b2) {
    extern __shared__ __half smh[];
    __half* sAh = smh; __half* sWh = smh + 8192;
    float* fx = (float*)(smh + 16384);
    float* stage = fx;
    float* sBias = fx + 12288; float* sG = fx + 12416; float* sB2 = fx + 12544;
    float* sRS = fx + 12672; float* sRQ = fx + 12928;
    uint32_t sAu = s2u(sAh), sWu = s2u(sWh);
    int tid = threadIdx.x, lane = tid & 31, wid = tid >> 5;
    int g = lane >> 2, t = lane & 3;
    int mbase = (wid & 3) * 32, nbase = (wid >> 2) * 64;

    cpa_h<64>(sWu, g_Wt + 16384, tid);   // We (slot 1)
    {
        uint32_t dst = s2u(stage);
        const float* src = E + (size_t)blockIdx.x * 128 * 48;
        #pragma unroll
        for (int i = tid; i < 1536; i += 256) CP16(dst + i * 16, src + i * 4);
    }
    CP_COMMIT();
    if (tid < 128) { sBias[tid] = bb[tid]; sG[tid] = gg[tid]; sB2[tid] = b2[tid]; }

    int cur = 0;
    for (int tile = blockIdx.x; tile < 1024; tile += gridDim.x) {
        int nxt = tile + gridDim.x;
        if (nxt < 1024) {
            uint32_t dst = s2u(stage + (1 - cur) * 6144);
            const float* src = E + (size_t)nxt * 128 * 48;
            #pragma unroll
            for (int i = tid; i < 1536; i += 256) CP16(dst + i * 16, src + i * 4);
            CP_COMMIT(); CP_WAIT1();
        } else {
            CP_WAIT0();
        }
        __syncthreads();
        const float* st = stage + cur * 6144;
        for (int i = tid; i < 1024; i += 256) {
            int r = i >> 3, gc = (i & 7) * 8;
            uint4 u;
            if (gc < 48) {
                const float* xp = st + r * 48 + gc;
                float4 v0 = *(const float4*)xp;
                float4 v1 = *(const float4*)(xp + 4);
                u.x = f2h2(v0.x, v0.y); u.y = f2h2(v0.z, v0.w);
                u.z = f2h2(v1.x, v1.y); u.w = f2h2(v1.z, v1.w);
            } else u = make_uint4(0, 0, 0, 0);
            *(uint4*)((char*)sAh + swzh<64>(r, gc) * 2) = u;
        }
        __syncthreads();

        float acc[2][8][4];
        zacc(acc);
        cta_gemm_h<4, 64>(sAu, sWu, lane, mbase, nbase, acc);

        float p[4] = {0, 0, 0, 0}, q[4] = {0, 0, 0, 0};
        #pragma unroll
        for (int mt = 0; mt < 2; ++mt)
            #pragma unroll
            for (int nt = 0; nt < 8; ++nt) {
                int c0 = nbase + nt * 8 + t * 2;
                float* d = acc[mt][nt];
                d[0] += sBias[c0]; d[1] += sBias[c0 + 1];
                d[2] += sBias[c0]; d[3] += sBias[c0 + 1];
                p[mt*2]   += d[0] + d[1];  q[mt*2]   += d[0]*d[0] + d[1]*d[1];
                p[mt*2+1] += d[2] + d[3];  q[mt*2+1] += d[2]*d[2] + d[3]*d[3];
            }
        #pragma unroll
        for (int i = 0; i < 4; ++i) {
            p[i] += __shfl_xor_sync(0xffffffffu, p[i], 1);
            p[i] += __shfl_xor_sync(0xffffffffu, p[i], 2);
            q[i] += __shfl_xor_sync(0xffffffffu, q[i], 1);
            q[i] += __shfl_xor_sync(0xffffffffu, q[i], 2);
        }
        int half_ = nbase >> 6;
        if (t == 0) {
            #pragma unroll
            for (int i = 0; i < 4; ++i) {
                int r = mbase + (i >> 1) * 16 + (i & 1) * 8 + g;
                sRS[r * 2 + half_] = p[i];
                sRQ[r * 2 + half_] = q[i];
            }
        }
        __syncthreads();
        #pragma unroll
        for (int mt = 0; mt < 2; ++mt)
            #pragma unroll
            for (int jj = 0; jj < 2; ++jj) {
                int r = mbase + mt * 16 + jj * 8 + g;
                float mu = (sRS[r * 2] + sRS[r * 2 + 1]) * (1.f / 128.f);
                float qq = sRQ[r * 2] + sRQ[r * 2 + 1];
                float var = (qq - 128.f * mu * mu) * (1.f / 127.f);
                float inv = 1.f / (sqrtf(fmaxf(var, 0.f)) + 1e-6f);
                #pragma unroll
                for (int nt = 0; nt < 8; ++nt) {
                    int c0 = nbase + nt * 8 + t * 2;
                    float* d = acc[mt][nt];
                    float v0 = sG[c0]     * (d[jj*2]   - mu) * inv + sB2[c0];
                    float v1 = sG[c0 + 1] * (d[jj*2+1] - mu) * inv + sB2[c0 + 1];
                    *(uint32_t*)(g_her + ((size_t)tile * 128 + r) * 128 + c0) = f2h2(v0, v1);
                }
            }
        __syncthreads();
        cur ^= 1;
    }
}

// ---------------- edge layer: persistent, resident weights ------------------
#define SM_EDGE (49152 * 2 + 896 * 4)
__global__ void __launch_bounds__(256, 2)
edge_layer_k(const int* __restrict__ Eidx, const float* __restrict__ mask,
             const float* __restrict__ Lb2, int layer) {
    extern __shared__ __half smh[];
    __half* sAh = smh; __half* sB0h = smh + 16384; __half* sB1h = smh + 32768;
    float* fx = (float*)(smh + 49152);
    float* sP1 = fx; float* sVm = fx + 512; float* sBb2 = fx + 640;
    int* sGidx = (int*)(fx + 768);
    uint32_t sAu = s2u(sAh), sB0u = s2u(sB0h), sB1u = s2u(sB1h);
    int tid = threadIdx.x, lane = tid & 31, wid = tid >> 5;
    int wbase = 2 + layer * 6;
    int mbase = (wid & 3) * 32, nbase = (wid >> 2) * 64;
    int g = lane >> 2, t = lane & 3;

    cpa_h<128>(sB0u, g_Wt + (size_t)(wbase + 3) * 16384, tid);  // W1q3
    cpa_h<128>(sB1u, g_Wt + (size_t)(wbase + 4) * 16384, tid);  // Lw2
    if (tid < 128) sBb2[tid] = Lb2[layer * 128 + tid];

    for (int tile = blockIdx.x; tile < 1024; tile += gridDim.x) {
        __syncthreads();           // protect metadata vs previous readers
        int base4 = tile * 4;
        if (tid < 128) {
            int nd = base4 + (tid >> 5);
            int idx = Eidx[nd * 32 + (tid & 31)];
            int gi = ((nd >> 11) << 11) + idx;
            sGidx[tid] = gi;
            sVm[tid] = mask[gi];
        }
        for (int i = tid; i < 512; i += 256)
            sP1[i] = g_P1[(size_t)base4 * 128 + i];
        cpa_h<128>(sAu, g_her + (size_t)tile * 16384, tid);
        CP_COMMIT(); CP_WAIT0(); __syncthreads();

        float acc[2][8][4];
        zacc(acc);
        cta_gemm_h<8, 128>(sAu, sB0u, lane, mbase, nbase, acc);
        __syncthreads();

        // epilogue1: relu(D + P1 + P23gather) -> sAh
        #pragma unroll
        for (int mt = 0; mt < 2; ++mt) {
            int r0 = mbase + mt * 16 + g, r1 = r0 + 8;
            const float* p23a = g_P23 + (size_t)sGidx[r0] * 128;
            const float* p23b = g_P23 + (size_t)sGidx[r1] * 128;
            const float* p1a = sP1 + ((r0 >> 5) << 7);
            const float* p1b = sP1 + ((r1 >> 5) << 7);
            #pragma unroll
            for (int nt = 0; nt < 8; ++nt) {
                int c0 = nbase + nt * 8 + t * 2;
                float* d = acc[mt][nt];
                float2 qa = *(const float2*)(p23a + c0);
                float2 qb = *(const float2*)(p23b + c0);
                *(uint32_t*)((char*)sAh + swzh<128>(r0, c0) * 2) =
                    f2h2(fmaxf(d[0] + qa.x + p1a[c0], 0.f), fmaxf(d[1] + qa.y + p1a[c0+1], 0.f));
                *(uint32_t*)((char*)sAh + swzh<128>(r1, c0) * 2) =
                    f2h2(fmaxf(d[2] + qb.x + p1b[c0], 0.f), fmaxf(d[3] + qb.y + p1b[c0+1], 0.f));
            }
        }
        __syncthreads();

        zacc(acc);
        cta_gemm_h<8, 128>(sAu, sB1u, lane, mbase, nbase, acc);

        // epilogue2: weighted segment sum of relu(D + b2)
        float part[8][2];
        #pragma unroll
        for (int nt = 0; nt < 8; ++nt) { part[nt][0] = 0.f; part[nt][1] = 0.f; }
        #pragma unroll
        for (int mt = 0; mt < 2; ++mt) {
            int r0 = mbase + mt * 16 + g, r1 = r0 + 8;
            float v0 = sVm[r0], v1 = sVm[r1];
            #pragma unroll
            for (int nt = 0; nt < 8; ++nt) {
                int c0 = nbase + nt * 8 + t * 2;
                float* d = acc[mt][nt];
                part[nt][0] += fmaxf(d[0] + sBb2[c0],   0.f) * v0
                             + fmaxf(d[2] + sBb2[c0],   0.f) * v1;
                part[nt][1] += fmaxf(d[1] + sBb2[c0+1], 0.f) * v0
                             + fmaxf(d[3] + sBb2[c0+1], 0.f) * v1;
            }
        }
        #pragma unroll
        for (int nt = 0; nt < 8; ++nt)
            #pragma unroll
            for (int j = 0; j < 2; ++j) {
                float v = part[nt][j];
                v += __shfl_xor_sync(0xffffffffu, v, 4);
                v += __shfl_xor_sync(0xffffffffu, v, 8);
                v += __shfl_xor_sync(0xffffffffu, v, 16);
                part[nt][j] = v;
            }
        if (g == 0) {
            int node = base4 + (wid & 3);
            #pragma unroll
            for (int nt = 0; nt < 8; ++nt) {
                int c0 = nbase + nt * 8 + t * 2;
                *(uint32_t*)(g_S2h + (size_t)node * 128 + c0) = f2h2(part[nt][0], part[nt][1]);
            }
        }
    }
}

// ---------------- shared proj phase: P1 = h@W0+b1 ; P23 = h@W1 + hS@W2 ------
__device__ __forceinline__ void proj_phase(uint32_t sA2u, uint32_t sA1u,
                                           uint32_t sW0u, uint32_t sW1u, uint32_t sW2u,
                                           const float* sBias1, int blk,
                                           int lane, int wid) {
    int mbase = (wid & 3) * 32, nbase = (wid >> 2) * 64;
    int g = lane >> 2, t = lane & 3;
    float acc[2][8][4];

    zacc(acc);
    cta_gemm_h<8, 128>(sA2u, sW0u, lane, mbase, nbase, acc);
    #pragma unroll
    for (int mt = 0; mt < 2; ++mt) {
        int r0 = mbase + mt * 16 + g;
        #pragma unroll
        for (int nt = 0; nt < 8; ++nt) {
            int c0 = nbase + nt * 8 + t * 2;
            float* d = acc[mt][nt];
            *(float2*)(g_P1 + ((size_t)blk * 128 + r0) * 128 + c0) =
                make_float2(d[0] + sBias1[c0], d[1] + sBias1[c0 + 1]);
            *(float2*)(g_P1 + ((size_t)blk * 128 + r0 + 8) * 128 + c0) =
                make_float2(d[2] + sBias1[c0], d[3] + sBias1[c0 + 1]);
        }
    }
    zacc(acc);
    cta_gemm_h<8, 128>(sA2u, sW1u, lane, mbase, nbase, acc);
    CP_WAIT0(); __syncthreads();
    cta_gemm_h<8, 128>(sA1u, sW2u, lane, mbase, nbase, acc);
    #pragma unroll
    for (int mt = 0; mt < 2; ++mt) {
        int r0 = mbase + mt * 16 + g;
        #pragma unroll
        for (int nt = 0; nt < 8; ++nt) {
            int c0 = nbase + nt * 8 + t * 2;
            float* d = acc[mt][nt];
            *(float2*)(g_P23 + ((size_t)blk * 128 + r0) * 128 + c0) = make_float2(d[0], d[1]);
            *(float2*)(g_P23 + ((size_t)blk * 128 + r0 + 8) * 128 + c0) = make_float2(d[2], d[3]);
        }
    }
}

// node kernels smem: A1, A2, W0, W1, W2 (16384 halfs each) + 1280 floats
#define SM_NP (5 * 32768 + 1280 * 4)

// ---------------- embed_node + proj(layer 0) --------------------------------
__global__ void __launch_bounds__(256)
embed_node_proj_k(const float* __restrict__ V, const float* __restrict__ bb,
                  const float* __restrict__ gg, const float* __restrict__ b2,
                  const float* __restrict__ Lb1) {
    extern __shared__ __half smh[];
    __half* sA1 = smh;            __half* sA2 = smh + 16384;
    __half* sW0 = smh + 32768;    __half* sW1 = smh + 49152;  __half* sW2 = smh + 65536;
    float* fx = (float*)(smh + 81920);
    float* sBias = fx; float* sG = fx + 128; float* sB2 = fx + 256;
    float* sBias1 = fx + 640;
    float* sRS = fx + 768; float* sRQ = fx + 1024;
    uint32_t sA1u = s2u(sA1), sA2u = s2u(sA2);
    uint32_t sW0u = s2u(sW0), sW1u = s2u(sW1), sW2u = s2u(sW2);
    int tid = threadIdx.x, lane = tid & 31, wid = tid >> 5, blk = blockIdx.x;
    int g = lane >> 2, t = lane & 3;
    int mbase = (wid & 3) * 32, nbase = (wid >> 2) * 64;

    cpa_h<64>(sW2u, g_Wt, tid);                                  // Wv (slot 0)
    cpa_h<128>(sW0u, g_Wt + (size_t)2 * 16384, tid);             // W1q0 (layer0)
    cpa_h<128>(sW1u, g_Wt + (size_t)3 * 16384, tid);             // W1q1
    CP_COMMIT();
    // V rows -> fp16 swizzled into sA1 (K=64)
    for (int i = tid; i < 1024; i += 256) {
        int r = i >> 3, gc = (i & 7) * 8;
        const float* xp = V + ((size_t)blk * 128 + r) * 64 + gc;
        float4 v0 = *(const float4*)xp;
        float4 v1 = *(const float4*)(xp + 4);
        uint4 u;
        u.x = f2h2(v0.x, v0.y); u.y = f2h2(v0.z, v0.w);
        u.z = f2h2(v1.x, v1.y); u.w = f2h2(v1.z, v1.w);
        *(uint4*)((char*)sA1 + swzh<64>(r, gc) * 2) = u;
    }
    if (tid < 128) {
        sBias[tid] = bb[tid]; sG[tid] = gg[tid]; sB2[tid] = b2[tid];
        sBias1[tid] = Lb1[tid];
    }
    CP_WAIT0(); __syncthreads();

    float acc[2][8][4];
    zacc(acc);
    cta_gemm_h<4, 64>(sA1u, sW2u, lane, mbase, nbase, acc);
    __syncthreads();
    cpa_h<128>(sA1u, g_hSr + (size_t)blk * 16384, tid);          // hS tile
    cpa_h<128>(sW2u, g_Wt + (size_t)4 * 16384, tid);             // W1q2
    CP_COMMIT();

    // LN epilogue -> g_h + sA2 fp16
    float p[4] = {0,0,0,0}, q[4] = {0,0,0,0};
    #pragma unroll
    for (int mt = 0; mt < 2; ++mt)
        #pragma unroll
        for (int nt = 0; nt < 8; ++nt) {
            int c0 = nbase + nt * 8 + t * 2;
            float* d = acc[mt][nt];
            d[0] += sBias[c0]; d[1] += sBias[c0 + 1];
            d[2] += sBias[c0]; d[3] += sBias[c0 + 1];
            p[mt*2]   += d[0] + d[1];  q[mt*2]   += d[0]*d[0] + d[1]*d[1];
            p[mt*2+1] += d[2] + d[3];  q[mt*2+1] += d[2]*d[2] + d[3]*d[3];
        }
    #pragma unroll
    for (int i = 0; i < 4; ++i) {
        p[i] += __shfl_xor_sync(0xffffffffu, p[i], 1);
        p[i] += __shfl_xor_sync(0xffffffffu, p[i], 2);
        q[i] += __shfl_xor_sync(0xffffffffu, q[i], 1);
        q[i] += __shfl_xor_sync(0xffffffffu, q[i], 2);
    }
    int half_ = nbase >> 6;
    if (t == 0) {
        #pragma unroll
        for (int i = 0; i < 4; ++i) {
            int r = mbase + (i >> 1) * 16 + (i & 1) * 8 + g;
            sRS[r * 2 + half_] = p[i];
            sRQ[r * 2 + half_] = q[i];
        }
    }
    __syncthreads();
    #pragma unroll
    for (int mt = 0; mt < 2; ++mt)
        #pragma unroll
        for (int jj = 0; jj < 2; ++jj) {
            int r = mbase + mt * 16 + jj * 8 + g;
            float mu = (sRS[r * 2] + sRS[r * 2 + 1]) * (1.f / 128.f);
            float qq = sRQ[r * 2] + sRQ[r * 2 + 1];
            float var = (qq - 128.f * mu * mu) * (1.f / 127.f);
            float inv = 1.f / (sqrtf(fmaxf(var, 0.f)) + 1e-6f);
            #pragma unroll
            for (int nt = 0; nt < 8; ++nt) {
                int c0 = nbase + nt * 8 + t * 2;
                float* d = acc[mt][nt];
                float v0 = sG[c0]     * (d[jj*2]   - mu) * inv + sB2[c0];
                float v1 = sG[c0 + 1] * (d[jj*2+1] - mu) * inv + sB2[c0 + 1];
                *(float2*)(g_h + ((size_t)blk * 128 + r) * 128 + c0) = make_float2(v0, v1);
                *(uint32_t*)((char*)sA2 + swzh<128>(r, c0) * 2) = f2h2(v0, v1);
            }
        }
    __syncthreads();
    proj_phase(sA2u, sA1u, sW0u, sW1u, sW2u, sBias1, blk, lane, wid);
}

// ---------------- node_fused: fin(layer) + proj(layer+1) --------------------
__global__ void __launch_bounds__(256)
node_fused_k(const float* __restrict__ mask, const float* __restrict__ Lb3,
             const float* __restrict__ Lng, const float* __restrict__ Lnb,
             const float* __restrict__ Lb1, int layer, int last,
             float* __restrict__ outp) {
    extern __shared__ __half smh[];
    __half* sA1 = smh;            __half* sA2 = smh + 16384;
    __half* sW0 = smh + 32768;    __half* sW1 = smh + 49152;  __half* sW2 = smh + 65536;
    float* fx = (float*)(smh + 81920);
    float* sB3 = fx; float* sLg = fx + 128; float* sLb = fx + 256;
    float* sVs = fx + 384; float* sMk = fx + 512; float* sBias1 = fx + 640;
    float* sRS = fx + 768; float* sRQ = fx + 1024;
    uint32_t sA1u = s2u(sA1), sA2u = s2u(sA2);
    uint32_t sW0u = s2u(sW0), sW1u = s2u(sW1), sW2u = s2u(sW2);
    int tid = threadIdx.x, lane = tid & 31, wid = tid >> 5, blk = blockIdx.x;
    int wbase = 2 + layer * 6, wnext = 2 + (layer + 1) * 6;
    int g = lane >> 2, t = lane & 3;
    int mbase = (wid & 3) * 32, nbase = (wid >> 2) * 64;

    cpa_h<128>(sA1u, g_S2h + (size_t)blk * 16384, tid);          // S2 tile
    cpa_h<128>(sW2u, g_Wt + (size_t)(wbase + 5) * 16384, tid);   // Lw3
    if (!last) {
        cpa_h<128>(sW0u, g_Wt + (size_t)(wnext + 0) * 16384, tid);
        cpa_h<128>(sW1u, g_Wt + (size_t)(wnext + 1) * 16384, tid);
    }
    CP_COMMIT();
    if (tid < 128) {
        sB3[tid] = Lb3[layer * 128 + tid];
        sLg[tid] = Lng[layer * 128 + tid];
        sLb[tid] = Lnb[layer * 128 + tid];
        sVs[tid] = g_vs[blk * 128 + tid];
        sMk[tid] = mask[blk * 128 + tid];
        if (!last) sBias1[tid] = Lb1[(layer + 1) * 128 + tid];
    }
    CP_WAIT0(); __syncthreads();

    float acc[2][8][4];
    zacc(acc);
    cta_gemm_h<8, 128>(sA1u, sW2u, lane, mbase, nbase, acc);
    __syncthreads();
    if (!last) {
        cpa_h<128>(sA1u, g_hSr + (size_t)blk * 16384, tid);      // hS tile
        cpa_h<128>(sW2u, g_Wt + (size_t)(wnext + 2) * 16384, tid);
        CP_COMMIT();
    }

    // fin epilogue: x = d/30 + vs*b3/30 + h_old ; LN
    const float i30 = 1.f / 30.f;
    float p[4] = {0,0,0,0}, q[4] = {0,0,0,0};
    #pragma unroll
    for (int mt = 0; mt < 2; ++mt) {
        int r0 = mbase + mt * 16 + g, r1 = r0 + 8;
        float vs0 = sVs[r0] * i30, vs1 = sVs[r1] * i30;
        #pragma unroll
        for (int nt = 0; nt < 8; ++nt) {
            int c0 = nbase + nt * 8 + t * 2;
            float* d = acc[mt][nt];
            float2 h0 = *(const float2*)(g_h + ((size_t)(blk * 128 + r0)) * 128 + c0);
            float2 h1 = *(const float2*)(g_h + ((size_t)(blk * 128 + r1)) * 128 + c0);
            d[0] = d[0] * i30 + vs0 * sB3[c0]     + h0.x;
            d[1] = d[1] * i30 + vs0 * sB3[c0 + 1] + h0.y;
            d[2] = d[2] * i30 + vs1 * sB3[c0]     + h1.x;
            d[3] = d[3] * i30 + vs1 * sB3[c0 + 1] + h1.y;
            p[mt*2]   += d[0] + d[1];  q[mt*2]   += d[0]*d[0] + d[1]*d[1];
            p[mt*2+1] += d[2] + d[3];  q[mt*2+1] += d[2]*d[2] + d[3]*d[3];
        }
    }
    #pragma unroll
    for (int i = 0; i < 4; ++i) {
        p[i] += __shfl_xor_sync(0xffffffffu, p[i], 1);
        p[i] += __shfl_xor_sync(0xffffffffu, p[i], 2);
        q[i] += __shfl_xor_sync(0xffffffffu, q[i], 1);
        q[i] += __shfl_xor_sync(0xffffffffu, q[i], 2);
    }
    int half_ = nbase >> 6;
    if (t == 0) {
        #pragma unroll
        for (int i = 0; i < 4; ++i) {
            int r = mbase + (i >> 1) * 16 + (i & 1) * 8 + g;
            sRS[r * 2 + half_] = p[i];
            sRQ[r * 2 + half_] = q[i];
        }
    }
    __syncthreads();
    #pragma unroll
    for (int mt = 0; mt < 2; ++mt)
        #pragma unroll
        for (int jj = 0; jj < 2; ++jj) {
            int r = mbase + mt * 16 + jj * 8 + g;
            float mu = (sRS[r * 2] + sRS[r * 2 + 1]) * (1.f / 128.f);
            float qq = sRQ[r * 2] + sRQ[r * 2 + 1];
            float var = (qq - 128.f * mu * mu) * (1.f / 127.f);
            float inv = 1.f / (sqrtf(fmaxf(var, 0.f)) + 1e-6f);
            float mk = sMk[r];
            #pragma unroll
            for (int nt = 0; nt < 8; ++nt) {
                int c0 = nbase + nt * 8 + t * 2;
                float* d = acc[mt][nt];
                float v0 = (sLg[c0]     * (d[jj*2]   - mu) * inv + sLb[c0])     * mk;
                float v1 = (sLg[c0 + 1] * (d[jj*2+1] - mu) * inv + sLb[c0 + 1]) * mk;
                size_t off = ((size_t)blk * 128 + r) * 128 + c0;
                if (last) {
                    *(float2*)(outp + off) = make_float2(v0, v1);
                } else {
                    *(float2*)(g_h + off) = make_float2(v0, v1);
                    *(uint32_t*)((char*)sA2 + swzh<128>(r, c0) * 2) = f2h2(v0, v1);
                }
            }
        }
    if (last) return;
    __syncthreads();
    proj_phase(sA2u, sA1u, sW0u, sW1u, sW2u, sBias1, blk, lane, wid);
}

// ---------------- launch ----------------
extern "C" void kernel_launch(void* const* d_in, const int* in_sizes, int n_in,
                              void* d_out, int out_size) {
    const float* V     = (const float*)d_in[0];
    const float* E     = (const float*)d_in[1];
    const float* hS    = (const float*)d_in[2];
    const int*   E_idx = (const int*)  d_in[3];
    const float* mask  = (const float*)d_in[4];
    const float* Wv_w  = (const float*)d_in[5];
    const float* Wv_b  = (const float*)d_in[6];
    const float* Wv_g  = (const float*)d_in[7];
    const float* Wv_b2 = (const float*)d_in[8];
    const float* We_w  = (const float*)d_in[9];
    const float* We_b  = (const float*)d_in[10];
    const float* We_g  = (const float*)d_in[11];
    const float* We_b2 = (const float*)d_in[12];
    const float* Lw1   = (const float*)d_in[13];
    const float* Lb1   = (const float*)d_in[14];
    const float* Lw2   = (const float*)d_in[15];
    const float* Lb2   = (const float*)d_in[16];
    const float* Lw3   = (const float*)d_in[17];
    const float* Lb3   = (const float*)d_in[18];
    const float* Ln_g  = (const float*)d_in[19];
    const float* Ln_b  = (const float*)d_in[20];
    float* out = (float*)d_out;

    cudaFuncSetAttribute(embed_edge_k,      cudaFuncAttributeMaxDynamicSharedMemorySize, SM_EE);
    cudaFuncSetAttribute(edge_layer_k,      cudaFuncAttributeMaxDynamicSharedMemorySize, SM_EDGE);
    cudaFuncSetAttribute(embed_node_proj_k, cudaFuncAttributeMaxDynamicSharedMemorySize, SM_NP);
    cudaFuncSetAttribute(node_fused_k,      cudaFuncAttributeMaxDynamicSharedMemorySize, SM_NP);

    pack_w<<<20, 256>>>(Wv_w, We_w, Lw1, Lw2, Lw3);
    pack_hs<<<128, 256>>>(hS);
    compute_vs<<<16, 256>>>(E_idx, mask);
    embed_node_proj_k<<<32, 256, SM_NP>>>(V, Wv_b, Wv_g, Wv_b2, Lb1);
    embed_edge_k<<<304, 256, SM_EE>>>(E, We_b, We_g, We_b2);

    for (int layer = 0; layer < 3; ++layer) {
        edge_layer_k<<<304, 256, SM_EDGE>>>(E_idx, mask, Lb2, layer);
        node_fused_k<<<32, 256, SM_NP>>>(mask, Lb3, Ln_g, Ln_b, Lb1,
                                         layer, layer == 2 ? 1 : 0, out);
    }
}

// round 9
// speedup vs baseline: 9.3047x; 1.1622x over previous
#include <cuda_runtime.h>
#include <cuda_fp16.h>
#include <cstdint>
#include <math.h>

#define NODES 4096
#define EDGES 131072

// ---------------- device scratch ----------------
__device__ __align__(256) __half g_her[EDGES * 128];
__device__ __align__(256) float  g_h  [NODES * 128];
__device__ __align__(256) __half g_hSr[NODES * 128];
__device__ __align__(256) float  g_P1 [NODES * 128];
__device__ __align__(256) float  g_P23[NODES * 128];
__device__ __align__(256) __half g_S2h[NODES * 128];
__device__ __align__(256) float  g_vs [NODES];
__device__ __align__(256) __half g_Wt [20 * 16384];

// ---------------- helpers ----------------
__device__ __forceinline__ uint32_t s2u(const void* p) {
    uint32_t a;
    asm("{ .reg .u64 t; cvta.to.shared.u64 t, %1; cvt.u32.u64 %0, t; }" : "=r"(a) : "l"(p));
    return a;
}
__device__ __forceinline__ uint32_t f2h2(float x, float y) {
    __half2 h = __floats2half2_rn(x, y);
    return *(uint32_t*)&h;
}
__device__ __forceinline__ void ldsm4(uint32_t d[4], uint32_t a) {
    asm volatile("ldmatrix.sync.aligned.m8n8.x4.shared.b16 {%0,%1,%2,%3}, [%4];"
                 : "=r"(d[0]), "=r"(d[1]), "=r"(d[2]), "=r"(d[3]) : "r"(a));
}
__device__ __forceinline__ void mma16(float d[4], const uint32_t a[4], uint32_t b0, uint32_t b1) {
    asm volatile("mma.sync.aligned.m16n8k16.row.col.f32.f16.f16.f32 "
                 "{%0,%1,%2,%3}, {%4,%5,%6,%7}, {%8,%9}, {%0,%1,%2,%3};"
                 : "+f"(d[0]), "+f"(d[1]), "+f"(d[2]), "+f"(d[3])
                 : "r"(a[0]), "r"(a[1]), "r"(a[2]), "r"(a[3]), "r"(b0), "r"(b1));
}
#define CP16(dst, src) asm volatile("cp.async.cg.shared.global [%0], [%1], 16;" :: "r"(dst), "l"(src))
#define CP_COMMIT()    asm volatile("cp.async.commit_group;")
#define CP_WAIT0()     asm volatile("cp.async.wait_group 0;" ::: "memory")
#define CP_WAIT1()     asm volatile("cp.async.wait_group 1;" ::: "memory")

template <int ROWH>
__device__ __forceinline__ int swzh(int r, int c) { return r * ROWH + (c ^ ((r & 7) << 3)); }

template <int ROWS, int ROWH>
__device__ __forceinline__ void cpa_h(uint32_t sDst, const __half* __restrict__ g, int tid) {
    const int NCH = ROWS * ROWH / 8;
    #pragma unroll 4
    for (int i = tid; i < NCH; i += 256) {
        int r = i / (ROWH / 8), c = (i % (ROWH / 8)) * 8;
        CP16(sDst + swzh<ROWH>(r, c) * 2, g + (size_t)r * ROWH + c);
    }
}

// ------------- 128-row CTA GEMM (edge kernels): 8 warps 4m x 2n, 32x64 -------
__device__ __forceinline__ void zacc8(float acc[2][8][4]) {
    #pragma unroll
    for (int i = 0; i < 2; ++i)
        #pragma unroll
        for (int j = 0; j < 8; ++j)
            #pragma unroll
            for (int k = 0; k < 4; ++k) acc[i][j][k] = 0.f;
}
template <int KH, int ROWH>
__device__ __forceinline__ void cta_gemm_h(uint32_t sAu, uint32_t sBu, int lane,
                                           int mbase, int nbase, float acc[2][8][4]) {
    int arow = lane & 15, acol = (lane >> 4) << 3;
    int bn = ((lane >> 4) & 1) * 8 + (lane & 7), bk = ((lane >> 3) & 1) * 8;
    #pragma unroll
    for (int k0 = 0; k0 < KH; ++k0) {
        int kh = k0 * 16;
        uint32_t a0[4], a1[4];
        ldsm4(a0, sAu + swzh<ROWH>(mbase + arow,      kh + acol) * 2);
        ldsm4(a1, sAu + swzh<ROWH>(mbase + 16 + arow, kh + acol) * 2);
        #pragma unroll
        for (int q8 = 0; q8 < 4; ++q8) {
            uint32_t b[4];
            ldsm4(b, sBu + swzh<ROWH>(nbase + q8 * 16 + bn, kh + bk) * 2);
            mma16(acc[0][q8 * 2],     a0, b[0], b[1]);
            mma16(acc[0][q8 * 2 + 1], a0, b[2], b[3]);
            mma16(acc[1][q8 * 2],     a1, b[0], b[1]);
            mma16(acc[1][q8 * 2 + 1], a1, b[2], b[3]);
        }
    }
}

// ------------- 64-row CTA GEMM (node kernels): 8 warps 2m x 4n, 32x32 --------
__device__ __forceinline__ void zacc4(float acc[2][4][4]) {
    #pragma unroll
    for (int i = 0; i < 2; ++i)
        #pragma unroll
        for (int j = 0; j < 4; ++j)
            #pragma unroll
            for (int k = 0; k < 4; ++k) acc[i][j][k] = 0.f;
}
template <int KH, int ROWH>
__device__ __forceinline__ void cta_gemm64(uint32_t sAu, uint32_t sBu, int lane,
                                           int mbase, int nbase, float acc[2][4][4]) {
    int arow = lane & 15, acol = (lane >> 4) << 3;
    int bn = ((lane >> 4) & 1) * 8 + (lane & 7), bk = ((lane >> 3) & 1) * 8;
    #pragma unroll
    for (int k0 = 0; k0 < KH; ++k0) {
        int kh = k0 * 16;
        uint32_t a0[4], a1[4];
        ldsm4(a0, sAu + swzh<ROWH>(mbase + arow,      kh + acol) * 2);
        ldsm4(a1, sAu + swzh<ROWH>(mbase + 16 + arow, kh + acol) * 2);
        #pragma unroll
        for (int q8 = 0; q8 < 2; ++q8) {
            uint32_t b[4];
            ldsm4(b, sBu + swzh<ROWH>(nbase + q8 * 16 + bn, kh + bk) * 2);
            mma16(acc[0][q8 * 2],     a0, b[0], b[1]);
            mma16(acc[0][q8 * 2 + 1], a0, b[2], b[3]);
            mma16(acc[1][q8 * 2],     a1, b[0], b[1]);
            mma16(acc[1][q8 * 2 + 1], a1, b[2], b[3]);
        }
    }
}

// ---------------- pack_all: weights + hS + vs in one launch ----------------
__global__ void pack_all(const float* __restrict__ Wv, const float* __restrict__ We,
                         const float* __restrict__ Lw1, const float* __restrict__ Lw2,
                         const float* __restrict__ Lw3, const float* __restrict__ hS,
                         const int* __restrict__ Eidx, const float* __restrict__ mask) {
    int m = blockIdx.x, tid = threadIdx.x;
    if (m < 20) {
        const float* src; int Kin, ROWH;
        if (m == 0)      { src = Wv; Kin = 64; ROWH = 64; }
        else if (m == 1) { src = We; Kin = 48; ROWH = 64; }
        else {
            int l = (m - 2) / 6, q = (m - 2) % 6;
            if (q < 4)       src = Lw1 + ((size_t)l * 512 + q * 128) * 128;
            else if (q == 4) src = Lw2 + (size_t)l * 16384;
            else             src = Lw3 + (size_t)l * 16384;
            Kin = 128; ROWH = 128;
        }
        __half* dst = g_Wt + (size_t)m * 16384;
        int tot = 128 * ROWH;
        for (int i = tid; i < tot; i += 256) {
            int n = i / ROWH, k = i % ROWH;
            dst[i] = (k < Kin) ? __float2half_rn(src[(size_t)k * 128 + n]) : __half(0.f);
        }
    } else if (m < 52) {
        int b = m - 20;
        const float* src = hS + (size_t)b * 16384;
        __half* dst = g_hSr + (size_t)b * 16384;
        for (int i = tid; i < 16384; i += 256) dst[i] = __float2half_rn(src[i]);
    } else {
        int nd = (m - 52) * 256 + tid;
        if (nd < NODES) {
            int b = nd >> 11;
            float s = 0.f;
            #pragma unroll 8
            for (int k = 0; k < 32; ++k) s += mask[(b << 11) + Eidx[nd * 32 + k]];
            g_vs[nd] = s;
        }
    }
}

// ---------------- embed_edge: persistent, double-buffered staging ----------
#define SM_EE (16384 * 2 + (12288 + 896) * 4)
__global__ void __launch_bounds__(256, 2)
embed_edge_k(const float* __restrict__ E, const float* __restrict__ bb,
             const float* __restrict__ gg, const float* __restrict__ b2) {
    extern __shared__ __half smh[];
    __half* sAh = smh; __half* sWh = smh + 8192;
    float* fx = (float*)(smh + 16384);
    float* stage = fx;
    float* sBias = fx + 12288; float* sG = fx + 12416; float* sB2 = fx + 12544;
    float* sRS = fx + 12672; float* sRQ = fx + 12928;
    uint32_t sAu = s2u(sAh), sWu = s2u(sWh);
    int tid = threadIdx.x, lane = tid & 31, wid = tid >> 5;
    int g = lane >> 2, t = lane & 3;
    int mbase = (wid & 3) * 32, nbase = (wid >> 2) * 64;

    cpa_h<128, 64>(sWu, g_Wt + 16384, tid);   // We
    {
        uint32_t dst = s2u(stage);
        const float* src = E + (size_t)blockIdx.x * 128 * 48;
        #pragma unroll
        for (int i = tid; i < 1536; i += 256) CP16(dst + i * 16, src + i * 4);
    }
    CP_COMMIT();
    if (tid < 128) { sBias[tid] = bb[tid]; sG[tid] = gg[tid]; sB2[tid] = b2[tid]; }

    int cur = 0;
    for (int tile = blockIdx.x; tile < 1024; tile += gridDim.x) {
        int nxt = tile + gridDim.x;
        if (nxt < 1024) {
            uint32_t dst = s2u(stage + (1 - cur) * 6144);
            const float* src = E + (size_t)nxt * 128 * 48;
            #pragma unroll
            for (int i = tid; i < 1536; i += 256) CP16(dst + i * 16, src + i * 4);
            CP_COMMIT(); CP_WAIT1();
        } else {
            CP_WAIT0();
        }
        __syncthreads();
        const float* st = stage + cur * 6144;
        for (int i = tid; i < 1024; i += 256) {
            int r = i >> 3, gc = (i & 7) * 8;
            uint4 u;
            if (gc < 48) {
                const float* xp = st + r * 48 + gc;
                float4 v0 = *(const float4*)xp;
                float4 v1 = *(const float4*)(xp + 4);
                u.x = f2h2(v0.x, v0.y); u.y = f2h2(v0.z, v0.w);
                u.z = f2h2(v1.x, v1.y); u.w = f2h2(v1.z, v1.w);
            } else u = make_uint4(0, 0, 0, 0);
            *(uint4*)((char*)sAh + swzh<64>(r, gc) * 2) = u;
        }
        __syncthreads();

        float acc[2][8][4];
        zacc8(acc);
        cta_gemm_h<4, 64>(sAu, sWu, lane, mbase, nbase, acc);

        float p[4] = {0, 0, 0, 0}, q[4] = {0, 0, 0, 0};
        #pragma unroll
        for (int mt = 0; mt < 2; ++mt)
            #pragma unroll
            for (int nt = 0; nt < 8; ++nt) {
                int c0 = nbase + nt * 8 + t * 2;
                float* d = acc[mt][nt];
                d[0] += sBias[c0]; d[1] += sBias[c0 + 1];
                d[2] += sBias[c0]; d[3] += sBias[c0 + 1];
                p[mt*2]   += d[0] + d[1];  q[mt*2]   += d[0]*d[0] + d[1]*d[1];
                p[mt*2+1] += d[2] + d[3];  q[mt*2+1] += d[2]*d[2] + d[3]*d[3];
            }
        #pragma unroll
        for (int i = 0; i < 4; ++i) {
            p[i] += __shfl_xor_sync(0xffffffffu, p[i], 1);
            p[i] += __shfl_xor_sync(0xffffffffu, p[i], 2);
            q[i] += __shfl_xor_sync(0xffffffffu, q[i], 1);
            q[i] += __shfl_xor_sync(0xffffffffu, q[i], 2);
        }
        int half_ = nbase >> 6;
        if (t == 0) {
            #pragma unroll
            for (int i = 0; i < 4; ++i) {
                int r = mbase + (i >> 1) * 16 + (i & 1) * 8 + g;
                sRS[r * 2 + half_] = p[i];
                sRQ[r * 2 + half_] = q[i];
            }
        }
        __syncthreads();
        #pragma unroll
        for (int mt = 0; mt < 2; ++mt)
            #pragma unroll
            for (int jj = 0; jj < 2; ++jj) {
                int r = mbase + mt * 16 + jj * 8 + g;
                float mu = (sRS[r * 2] + sRS[r * 2 + 1]) * (1.f / 128.f);
                float qq = sRQ[r * 2] + sRQ[r * 2 + 1];
                float var = (qq - 128.f * mu * mu) * (1.f / 127.f);
                float inv = 1.f / (sqrtf(fmaxf(var, 0.f)) + 1e-6f);
                #pragma unroll
                for (int nt = 0; nt < 8; ++nt) {
                    int c0 = nbase + nt * 8 + t * 2;
                    float* d = acc[mt][nt];
                    float v0 = sG[c0]     * (d[jj*2]   - mu) * inv + sB2[c0];
                    float v1 = sG[c0 + 1] * (d[jj*2+1] - mu) * inv + sB2[c0 + 1];
                    *(uint32_t*)(g_her + ((size_t)tile * 128 + r) * 128 + c0) = f2h2(v0, v1);
                }
            }
        __syncthreads();
        cur ^= 1;
    }
}

// ---------------- edge layer: persistent, resident weights, A prefetch ------
#define SM_EDGE (49152 * 2 + 896 * 4)
__global__ void __launch_bounds__(256, 2)
edge_layer_k(const int* __restrict__ Eidx, const float* __restrict__ mask,
             const float* __restrict__ Lb2, int layer) {
    extern __shared__ __half smh[];
    __half* sAh = smh; __half* sB0h = smh + 16384; __half* sB1h = smh + 32768;
    float* fx = (float*)(smh + 49152);
    float* sP1 = fx; float* sVm = fx + 512; float* sBb2 = fx + 640;
    int* sGidx = (int*)(fx + 768);
    uint32_t sAu = s2u(sAh), sB0u = s2u(sB0h), sB1u = s2u(sB1h);
    int tid = threadIdx.x, lane = tid & 31, wid = tid >> 5;
    int wbase = 2 + layer * 6;
    int mbase = (wid & 3) * 32, nbase = (wid >> 2) * 64;
    int g = lane >> 2, t = lane & 3;

    cpa_h<128, 128>(sB0u, g_Wt + (size_t)(wbase + 3) * 16384, tid);  // W1q3
    cpa_h<128, 128>(sB1u, g_Wt + (size_t)(wbase + 4) * 16384, tid);  // Lw2
    if ((int)blockIdx.x < 1024)
        cpa_h<128, 128>(sAu, g_her + (size_t)blockIdx.x * 16384, tid);
    CP_COMMIT();
    if (tid < 128) sBb2[tid] = Lb2[layer * 128 + tid];

    for (int tile = blockIdx.x; tile < 1024; tile += gridDim.x) {
        __syncthreads();           // prev users of metadata/sAh done
        int base4 = tile * 4;
        if (tid < 128) {
            int nd = base4 + (tid >> 5);
            int idx = Eidx[nd * 32 + (tid & 31)];
            int gi = ((nd >> 11) << 11) + idx;
            sGidx[tid] = gi;
            sVm[tid] = mask[gi];
        }
        for (int i = tid; i < 512; i += 256)
            sP1[i] = g_P1[(size_t)base4 * 128 + i];
        CP_WAIT0(); __syncthreads();

        float acc[2][8][4];
        zacc8(acc);
        cta_gemm_h<8, 128>(sAu, sB0u, lane, mbase, nbase, acc);
        __syncthreads();

        // epilogue1: relu(D + P1 + P23gather) -> sAh
        #pragma unroll
        for (int mt = 0; mt < 2; ++mt) {
            int r0 = mbase + mt * 16 + g, r1 = r0 + 8;
            const float* p23a = g_P23 + (size_t)sGidx[r0] * 128;
            const float* p23b = g_P23 + (size_t)sGidx[r1] * 128;
            const float* p1a = sP1 + ((r0 >> 5) << 7);
            const float* p1b = sP1 + ((r1 >> 5) << 7);
            #pragma unroll
            for (int nt = 0; nt < 8; ++nt) {
                int c0 = nbase + nt * 8 + t * 2;
                float* d = acc[mt][nt];
                float2 qa = *(const float2*)(p23a + c0);
                float2 qb = *(const float2*)(p23b + c0);
                *(uint32_t*)((char*)sAh + swzh<128>(r0, c0) * 2) =
                    f2h2(fmaxf(d[0] + qa.x + p1a[c0], 0.f), fmaxf(d[1] + qa.y + p1a[c0+1], 0.f));
                *(uint32_t*)((char*)sAh + swzh<128>(r1, c0) * 2) =
                    f2h2(fmaxf(d[2] + qb.x + p1b[c0], 0.f), fmaxf(d[3] + qb.y + p1b[c0+1], 0.f));
            }
        }
        __syncthreads();

        zacc8(acc);
        cta_gemm_h<8, 128>(sAu, sB1u, lane, mbase, nbase, acc);
        __syncthreads();                       // all warps done reading sAh

        int nxt = tile + gridDim.x;            // prefetch next A during epilogue2
        if (nxt < 1024) {
            cpa_h<128, 128>(sAu, g_her + (size_t)nxt * 16384, tid);
            CP_COMMIT();
        }

        // epilogue2: weighted segment sum of relu(D + b2)
        float part[8][2];
        #pragma unroll
        for (int nt = 0; nt < 8; ++nt) { part[nt][0] = 0.f; part[nt][1] = 0.f; }
        #pragma unroll
        for (int mt = 0; mt < 2; ++mt) {
            int r0 = mbase + mt * 16 + g, r1 = r0 + 8;
            float v0 = sVm[r0], v1 = sVm[r1];
            #pragma unroll
            for (int nt = 0; nt < 8; ++nt) {
                int c0 = nbase + nt * 8 + t * 2;
                float* d = acc[mt][nt];
                part[nt][0] += fmaxf(d[0] + sBb2[c0],   0.f) * v0
                             + fmaxf(d[2] + sBb2[c0],   0.f) * v1;
                part[nt][1] += fmaxf(d[1] + sBb2[c0+1], 0.f) * v0
                             + fmaxf(d[3] + sBb2[c0+1], 0.f) * v1;
            }
        }
        #pragma unroll
        for (int nt = 0; nt < 8; ++nt)
            #pragma unroll
            for (int j = 0; j < 2; ++j) {
                float v = part[nt][j];
                v += __shfl_xor_sync(0xffffffffu, v, 4);
                v += __shfl_xor_sync(0xffffffffu, v, 8);
                v += __shfl_xor_sync(0xffffffffu, v, 16);
                part[nt][j] = v;
            }
        if (g == 0) {
            int node = base4 + (wid & 3);
            #pragma unroll
            for (int nt = 0; nt < 8; ++nt) {
                int c0 = nbase + nt * 8 + t * 2;
                *(uint32_t*)(g_S2h + (size_t)node * 128 + c0) = f2h2(part[nt][0], part[nt][1]);
            }
        }
    }
}

// ---------------- proj phase (M=64): P1 = h@W0+b1 ; P23 = h@W1 + hS@W2 ------
__device__ __forceinline__ void proj_phase64(uint32_t sA2u, uint32_t sA1u,
                                             uint32_t sW0u, uint32_t sW1u, uint32_t sW2u,
                                             const float* sBias1, int blk,
                                             int lane, int wid) {
    int mbase = (wid & 1) * 32, nbase = (wid >> 1) * 32;
    int g = lane >> 2, t = lane & 3;
    float acc[2][4][4];

    zacc4(acc);
    cta_gemm64<8, 128>(sA2u, sW0u, lane, mbase, nbase, acc);
    #pragma unroll
    for (int mt = 0; mt < 2; ++mt) {
        int r0 = mbase + mt * 16 + g;
        #pragma unroll
        for (int nt = 0; nt < 4; ++nt) {
            int c0 = nbase + nt * 8 + t * 2;
            float* d = acc[mt][nt];
            *(float2*)(g_P1 + ((size_t)blk * 64 + r0) * 128 + c0) =
                make_float2(d[0] + sBias1[c0], d[1] + sBias1[c0 + 1]);
            *(float2*)(g_P1 + ((size_t)blk * 64 + r0 + 8) * 128 + c0) =
                make_float2(d[2] + sBias1[c0], d[3] + sBias1[c0 + 1]);
        }
    }
    zacc4(acc);
    cta_gemm64<8, 128>(sA2u, sW1u, lane, mbase, nbase, acc);
    CP_WAIT0(); __syncthreads();
    cta_gemm64<8, 128>(sA1u, sW2u, lane, mbase, nbase, acc);
    #pragma unroll
    for (int mt = 0; mt < 2; ++mt) {
        int r0 = mbase + mt * 16 + g;
        #pragma unroll
        for (int nt = 0; nt < 4; ++nt) {
            int c0 = nbase + nt * 8 + t * 2;
            float* d = acc[mt][nt];
            *(float2*)(g_P23 + ((size_t)blk * 64 + r0) * 128 + c0) = make_float2(d[0], d[1]);
            *(float2*)(g_P23 + ((size_t)blk * 64 + r0 + 8) * 128 + c0) = make_float2(d[2], d[3]);
        }
    }
}

// node kernels smem: sA1 8192h, sA2 8192h, W0/W1/W2 16384h each + 1152 floats
#define SM_NP ((8192 * 2 + 3 * 16384) * 2 + 1152 * 4)

// ---------------- embed_node + proj(layer 0), M=64, grid 64 -----------------
__global__ void __launch_bounds__(256)
embed_node_proj_k(const float* __restrict__ V, const float* __restrict__ bb,
                  const float* __restrict__ gg, const float* __restrict__ b2,
                  const float* __restrict__ Lb1) {
    extern __shared__ __half smh[];
    __half* sA1 = smh;            __half* sA2 = smh + 8192;
    __half* sW0 = smh + 16384;    __half* sW1 = smh + 32768;  __half* sW2 = smh + 49152;
    float* fx = (float*)(smh + 65536);
    float* sBias = fx; float* sG = fx + 128; float* sB2 = fx + 256;
    float* sBias1 = fx + 384;
    float* sRS = fx + 512; float* sRQ = fx + 768;   // 64*4 each
    uint32_t sA1u = s2u(sA1), sA2u = s2u(sA2);
    uint32_t sW0u = s2u(sW0), sW1u = s2u(sW1), sW2u = s2u(sW2);
    int tid = threadIdx.x, lane = tid & 31, wid = tid >> 5, blk = blockIdx.x;
    int g = lane >> 2, t = lane & 3;
    int mbase = (wid & 1) * 32, nbase = (wid >> 1) * 32;
    int ng = wid >> 1;

    cpa_h<128, 64>(sW2u, g_Wt, tid);                              // Wv
    cpa_h<128, 128>(sW0u, g_Wt + (size_t)2 * 16384, tid);         // W1q0
    cpa_h<128, 128>(sW1u, g_Wt + (size_t)3 * 16384, tid);         // W1q1
    CP_COMMIT();
    // V rows (64 x 64) -> fp16 swizzled into sA1
    for (int i = tid; i < 512; i += 256) {
        int r = i >> 3, gc = (i & 7) * 8;
        const float* xp = V + ((size_t)blk * 64 + r) * 64 + gc;
        float4 v0 = *(const float4*)xp;
        float4 v1 = *(const float4*)(xp + 4);
        uint4 u;
        u.x = f2h2(v0.x, v0.y); u.y = f2h2(v0.z, v0.w);
        u.z = f2h2(v1.x, v1.y); u.w = f2h2(v1.z, v1.w);
        *(uint4*)((char*)sA1 + swzh<64>(r, gc) * 2) = u;
    }
    if (tid < 128) {
        sBias[tid] = bb[tid]; sG[tid] = gg[tid]; sB2[tid] = b2[tid];
        sBias1[tid] = Lb1[tid];
    }
    CP_WAIT0(); __syncthreads();

    float acc[2][4][4];
    zacc4(acc);
    cta_gemm64<4, 64>(sA1u, sW2u, lane, mbase, nbase, acc);
    __syncthreads();
    cpa_h<64, 128>(sA1u, g_hSr + (size_t)blk * 8192, tid);        // hS tile
    cpa_h<128, 128>(sW2u, g_Wt + (size_t)4 * 16384, tid);         // W1q2
    CP_COMMIT();

    // LN epilogue -> g_h + sA2 fp16
    float p[4] = {0,0,0,0}, q[4] = {0,0,0,0};
    #pragma unroll
    for (int mt = 0; mt < 2; ++mt)
        #pragma unroll
        for (int nt = 0; nt < 4; ++nt) {
            int c0 = nbase + nt * 8 + t * 2;
            float* d = acc[mt][nt];
            d[0] += sBias[c0]; d[1] += sBias[c0 + 1];
            d[2] += sBias[c0]; d[3] += sBias[c0 + 1];
            p[mt*2]   += d[0] + d[1];  q[mt*2]   += d[0]*d[0] + d[1]*d[1];
            p[mt*2+1] += d[2] + d[3];  q[mt*2+1] += d[2]*d[2] + d[3]*d[3];
        }
    #pragma unroll
    for (int i = 0; i < 4; ++i) {
        p[i] += __shfl_xor_sync(0xffffffffu, p[i], 1);
        p[i] += __shfl_xor_sync(0xffffffffu, p[i], 2);
        q[i] += __shfl_xor_sync(0xffffffffu, q[i], 1);
        q[i] += __shfl_xor_sync(0xffffffffu, q[i], 2);
    }
    if (t == 0) {
        #pragma unroll
        for (int i = 0; i < 4; ++i) {
            int r = mbase + (i >> 1) * 16 + (i & 1) * 8 + g;
            sRS[r * 4 + ng] = p[i];
            sRQ[r * 4 + ng] = q[i];
        }
    }
    __syncthreads();
    #pragma unroll
    for (int mt = 0; mt < 2; ++mt)
        #pragma unroll
        for (int jj = 0; jj < 2; ++jj) {
            int r = mbase + mt * 16 + jj * 8 + g;
            float mu = (sRS[r*4] + sRS[r*4+1] + sRS[r*4+2] + sRS[r*4+3]) * (1.f / 128.f);
            float qq = sRQ[r*4] + sRQ[r*4+1] + sRQ[r*4+2] + sRQ[r*4+3];
            float var = (qq - 128.f * mu * mu) * (1.f / 127.f);
            float inv = 1.f / (sqrtf(fmaxf(var, 0.f)) + 1e-6f);
            #pragma unroll
            for (int nt = 0; nt < 4; ++nt) {
                int c0 = nbase + nt * 8 + t * 2;
                float* d = acc[mt][nt];
                float v0 = sG[c0]     * (d[jj*2]   - mu) * inv + sB2[c0];
                float v1 = sG[c0 + 1] * (d[jj*2+1] - mu) * inv + sB2[c0 + 1];
                *(float2*)(g_h + ((size_t)blk * 64 + r) * 128 + c0) = make_float2(v0, v1);
                *(uint32_t*)((char*)sA2 + swzh<128>(r, c0) * 2) = f2h2(v0, v1);
            }
        }
    __syncthreads();
    proj_phase64(sA2u, sA1u, sW0u, sW1u, sW2u, sBias1, blk, lane, wid);
}

// ---------------- node_fused: fin(layer) + proj(layer+1), M=64, grid 64 -----
__global__ void __launch_bounds__(256)
node_fused_k(const float* __restrict__ mask, const float* __restrict__ Lb3,
             const float* __restrict__ Lng, const float* __restrict__ Lnb,
             const float* __restrict__ Lb1, int layer, int last,
             float* __restrict__ outp) {
    extern __shared__ __half smh[];
    __half* sA1 = smh;            __half* sA2 = smh + 8192;
    __half* sW0 = smh + 16384;    __half* sW1 = smh + 32768;  __half* sW2 = smh + 49152;
    float* fx = (float*)(smh + 65536);
    float* sB3 = fx; float* sLg = fx + 128; float* sLb = fx + 256;
    float* sBias1 = fx + 384;
    float* sRS = fx + 512; float* sRQ = fx + 768;
    float* sVs = fx + 1024; float* sMk = fx + 1088;      // 64 each
    uint32_t sA1u = s2u(sA1), sA2u = s2u(sA2);
    uint32_t sW0u = s2u(sW0), sW1u = s2u(sW1), sW2u = s2u(sW2);
    int tid = threadIdx.x, lane = tid & 31, wid = tid >> 5, blk = blockIdx.x;
    int wbase = 2 + layer * 6, wnext = 2 + (layer + 1) * 6;
    int g = lane >> 2, t = lane & 3;
    int mbase = (wid & 1) * 32, nbase = (wid >> 1) * 32;
    int ng = wid >> 1;

    cpa_h<64, 128>(sA1u, g_S2h + (size_t)blk * 8192, tid);        // S2 tile
    cpa_h<128, 128>(sW2u, g_Wt + (size_t)(wbase + 5) * 16384, tid);  // Lw3
    if (!last) {
        cpa_h<128, 128>(sW0u, g_Wt + (size_t)(wnext + 0) * 16384, tid);
        cpa_h<128, 128>(sW1u, g_Wt + (size_t)(wnext + 1) * 16384, tid);
    }
    CP_COMMIT();
    if (tid < 128) {
        sB3[tid] = Lb3[layer * 128 + tid];
        sLg[tid] = Lng[layer * 128 + tid];
        sLb[tid] = Lnb[layer * 128 + tid];
        if (!last) sBias1[tid] = Lb1[(layer + 1) * 128 + tid];
    }
    if (tid < 64) {
        sVs[tid] = g_vs[blk * 64 + tid];
        sMk[tid] = mask[blk * 64 + tid];
    }
    CP_WAIT0(); __syncthreads();

    float acc[2][4][4];
    zacc4(acc);
    cta_gemm64<8, 128>(sA1u, sW2u, lane, mbase, nbase, acc);
    __syncthreads();
    if (!last) {
        cpa_h<64, 128>(sA1u, g_hSr + (size_t)blk * 8192, tid);    // hS tile
        cpa_h<128, 128>(sW2u, g_Wt + (size_t)(wnext + 2) * 16384, tid);
        CP_COMMIT();
    }

    // fin epilogue: x = d/30 + vs*b3/30 + h_old ; LN
    const float i30 = 1.f / 30.f;
    float p[4] = {0,0,0,0}, q[4] = {0,0,0,0};
    #pragma unroll
    for (int mt = 0; mt < 2; ++mt) {
        int r0 = mbase + mt * 16 + g, r1 = r0 + 8;
        float vs0 = sVs[r0] * i30, vs1 = sVs[r1] * i30;
        #pragma unroll
        for (int nt = 0; nt < 4; ++nt) {
            int c0 = nbase + nt * 8 + t * 2;
            float* d = acc[mt][nt];
            float2 h0 = *(const float2*)(g_h + ((size_t)(blk * 64 + r0)) * 128 + c0);
            float2 h1 = *(const float2*)(g_h + ((size_t)(blk * 64 + r1)) * 128 + c0);
            d[0] = d[0] * i30 + vs0 * sB3[c0]     + h0.x;
            d[1] = d[1] * i30 + vs0 * sB3[c0 + 1] + h0.y;
            d[2] = d[2] * i30 + vs1 * sB3[c0]     + h1.x;
            d[3] = d[3] * i30 + vs1 * sB3[c0 + 1] + h1.y;
            p[mt*2]   += d[0] + d[1];  q[mt*2]   += d[0]*d[0] + d[1]*d[1];
            p[mt*2+1] += d[2] + d[3];  q[mt*2+1] += d[2]*d[2] + d[3]*d[3];
        }
    }
    #pragma unroll
    for (int i = 0; i < 4; ++i) {
        p[i] += __shfl_xor_sync(0xffffffffu, p[i], 1);
        p[i] += __shfl_xor_sync(0xffffffffu, p[i], 2);
        q[i] += __shfl_xor_sync(0xffffffffu, q[i], 1);
        q[i] += __shfl_xor_sync(0xffffffffu, q[i], 2);
    }
    if (t == 0) {
        #pragma unroll
        for (int i = 0; i < 4; ++i) {
            int r = mbase + (i >> 1) * 16 + (i & 1) * 8 + g;
            sRS[r * 4 + ng] = p[i];
            sRQ[r * 4 + ng] = q[i];
        }
    }
    __syncthreads();
    #pragma unroll
    for (int mt = 0; mt < 2; ++mt)
        #pragma unroll
        for (int jj = 0; jj < 2; ++jj) {
            int r = mbase + mt * 16 + jj * 8 + g;
            float mu = (sRS[r*4] + sRS[r*4+1] + sRS[r*4+2] + sRS[r*4+3]) * (1.f / 128.f);
            float qq = sRQ[r*4] + sRQ[r*4+1] + sRQ[r*4+2] + sRQ[r*4+3];
            float var = (qq - 128.f * mu * mu) * (1.f / 127.f);
            float inv = 1.f / (sqrtf(fmaxf(var, 0.f)) + 1e-6f);
            float mk = sMk[r];
            #pragma unroll
            for (int nt = 0; nt < 4; ++nt) {
                int c0 = nbase + nt * 8 + t * 2;
                float* d = acc[mt][nt];
                float v0 = (sLg[c0]     * (d[jj*2]   - mu) * inv + sLb[c0])     * mk;
                float v1 = (sLg[c0 + 1] * (d[jj*2+1] - mu) * inv + sLb[c0 + 1]) * mk;
                size_t off = ((size_t)blk * 64 + r) * 128 + c0;
                if (last) {
                    *(float2*)(outp + off) = make_float2(v0, v1);
                } else {
                    *(float2*)(g_h + off) = make_float2(v0, v1);
                    *(uint32_t*)((char*)sA2 + swzh<128>(r, c0) * 2) = f2h2(v0, v1);
                }
            }
        }
    if (last) return;
    __syncthreads();
    proj_phase64(sA2u, sA1u, sW0u, sW1u, sW2u, sBias1, blk, lane, wid);
}

// ---------------- launch ----------------
extern "C" void kernel_launch(void* const* d_in, const int* in_sizes, int n_in,
                              void* d_out, int out_size) {
    const float* V     = (const float*)d_in[0];
    const float* E     = (const float*)d_in[1];
    const float* hS    = (const float*)d_in[2];
    const int*   E_idx = (const int*)  d_in[3];
    const float* mask  = (const float*)d_in[4];
    const float* Wv_w  = (const float*)d_in[5];
    const float* Wv_b  = (const float*)d_in[6];
    const float* Wv_g  = (const float*)d_in[7];
    const float* Wv_b2 = (const float*)d_in[8];
    const float* We_w  = (const float*)d_in[9];
    const float* We_b  = (const float*)d_in[10];
    const float* We_g  = (const float*)d_in[11];
    const float* We_b2 = (const float*)d_in[12];
    const float* Lw1   = (const float*)d_in[13];
    const float* Lb1   = (const float*)d_in[14];
    const float* Lw2   = (const float*)d_in[15];
    const float* Lb2   = (const float*)d_in[16];
    const float* Lw3   = (const float*)d_in[17];
    const float* Lb3   = (const float*)d_in[18];
    const float* Ln_g  = (const float*)d_in[19];
    const float* Ln_b  = (const float*)d_in[20];
    float* out = (float*)d_out;

    cudaFuncSetAttribute(embed_edge_k,      cudaFuncAttributeMaxDynamicSharedMemorySize, SM_EE);
    cudaFuncSetAttribute(edge_layer_k,      cudaFuncAttributeMaxDynamicSharedMemorySize, SM_EDGE);
    cudaFuncSetAttribute(embed_node_proj_k, cudaFuncAttributeMaxDynamicSharedMemorySize, SM_NP);
    cudaFuncSetAttribute(node_fused_k,      cudaFuncAttributeMaxDynamicSharedMemorySize, SM_NP);

    pack_all<<<68, 256>>>(Wv_w, We_w, Lw1, Lw2, Lw3, hS, E_idx, mask);
    embed_node_proj_k<<<64, 256, SM_NP>>>(V, Wv_b, Wv_g, Wv_b2, Lb1);
    embed_edge_k<<<304, 256, SM_EE>>>(E, We_b, We_g, We_b2);

    for (int layer = 0; layer < 3; ++layer) {
        edge_layer_k<<<304, 256, SM_EDGE>>>(E_idx, mask, Lb2, layer);
        node_fused_k<<<64, 256, SM_NP>>>(mask, Lb3, Ln_g, Ln_b, Lb1,
                                         layer, layer == 2 ? 1 : 0, out);
    }
}